// round 3
// baseline (speedup 1.0000x reference)
#include <cuda_runtime.h>
#include <math.h>

// Problem constants
#define NB 128      // batch
#define SS 64       // initial sequence length
#define DD 512      // model dim
#define CHD 2048    // hidden dim of GRC fc1 / per-group width of fc2 output
#define SPLITK 16

// ---------------- device scratch (no allocations allowed) ----------------
__device__ float d_cs[NB * SS * DD];        // chart states, slot-addressed
__device__ float d_C0[NB * SS * DD];        // init GEMM output
__device__ float d_part[SPLITK * NB * CHD]; // split-K partial sums (shared fc1/fc2)
__device__ float d_h[NB * CHD];             // fc1 activations
__device__ float d_xcat[NB * 1024];         // [l, r] concat for selected pairs
__device__ int   d_idx[NB * SS];            // active slot list per row
__device__ int   d_slotL[NB];
__device__ int   d_flag[NB];

__device__ __forceinline__ float gelu_f(float x) {
    float x3 = x * x * x;
    return 0.5f * x * (1.0f + tanhf(0.7978845608028654f * (x + 0.044715f * x3)));
}
__device__ __forceinline__ float sigm_f(float x) {
    return 1.0f / (1.0f + expf(-x));
}

// ---------------- fp32 SGEMM, double-buffered, packed f32x2 math ----------------
// A: MxK row-major, B: KxN row-major. Block tile 128x128, 8x8 per thread,
// deterministic split-K via blockIdx.z writing disjoint partial buffers.
// A tile is stored DUPLICATED in smem (As[k][2r]=As[k][2r+1]=A[r][k]) so the
// broadcast operand of fma.rn.f32x2 is a natural 64-bit shared load; B pairs
// come straight out of LDS.128 as packed register pairs. Each packed half
// rounds exactly like scalar FFMA -> bit-identical results.
__global__ __launch_bounds__(256, 2) void sgemm_k(
    const float* __restrict__ A, const float* __restrict__ B, float* __restrict__ Cp,
    int M, int N, int K, int kc)
{
    __shared__ __align__(16) float As[2][16][256];   // duplicated A tile
    __shared__ __align__(16) float Bs[2][16][128];
    const int tid = threadIdx.x;
    const int tx = tid & 15;
    const int ty = tid >> 4;
    const int m0 = blockIdx.y * 128;
    const int n0 = blockIdx.x * 128;
    const int k0 = blockIdx.z * kc;
    const int nk = kc >> 4;

    unsigned long long accp[8][4];   // 8 rows x 4 packed column-pairs
#pragma unroll
    for (int i = 0; i < 8; i++)
#pragma unroll
        for (int j = 0; j < 4; j++) accp[i][j] = 0ull;

    const int arow = tid >> 2;          // 0..63
    const int ac4  = (tid & 3) << 2;    // 0,4,8,12
    const int brow = tid >> 5;          // 0..7
    const int bc4  = (tid & 31) << 2;   // 0..124

    const float* Ap = A + (size_t)(m0 + arow) * K + k0 + ac4;
    const float* Bp = B + (size_t)(k0 + brow) * N + n0 + bc4;

    // prologue: load tile 0
    float4 a0 = *(const float4*)(Ap);
    float4 a1 = *(const float4*)(Ap + (size_t)64 * K);
    float4 b0 = *(const float4*)(Bp);
    float4 b1 = *(const float4*)(Bp + (size_t)8 * N);
    {
        *(float2*)&As[0][ac4 + 0][2 * arow] = make_float2(a0.x, a0.x);
        *(float2*)&As[0][ac4 + 1][2 * arow] = make_float2(a0.y, a0.y);
        *(float2*)&As[0][ac4 + 2][2 * arow] = make_float2(a0.z, a0.z);
        *(float2*)&As[0][ac4 + 3][2 * arow] = make_float2(a0.w, a0.w);
        *(float2*)&As[0][ac4 + 0][2 * (arow + 64)] = make_float2(a1.x, a1.x);
        *(float2*)&As[0][ac4 + 1][2 * (arow + 64)] = make_float2(a1.y, a1.y);
        *(float2*)&As[0][ac4 + 2][2 * (arow + 64)] = make_float2(a1.z, a1.z);
        *(float2*)&As[0][ac4 + 3][2 * (arow + 64)] = make_float2(a1.w, a1.w);
        *(float4*)&Bs[0][brow][bc4]     = b0;
        *(float4*)&Bs[0][brow + 8][bc4] = b1;
    }
    __syncthreads();

    int buf = 0;
    for (int t = 0; t < nk; t++) {
        if (t + 1 < nk) {   // prefetch next tile into registers (overlaps compute)
            const float* Apn = Ap + (t + 1) * 16;
            const float* Bpn = Bp + (size_t)(t + 1) * 16 * N;
            a0 = *(const float4*)(Apn);
            a1 = *(const float4*)(Apn + (size_t)64 * K);
            b0 = *(const float4*)(Bpn);
            b1 = *(const float4*)(Bpn + (size_t)8 * N);
        }
#pragma unroll
        for (int kk = 0; kk < 16; kk++) {
            unsigned long long avp[8], bvp[4];
            *(ulonglong2*)(avp + 0) = *(const ulonglong2*)&As[buf][kk][ty * 16 + 0];
            *(ulonglong2*)(avp + 2) = *(const ulonglong2*)&As[buf][kk][ty * 16 + 4];
            *(ulonglong2*)(avp + 4) = *(const ulonglong2*)&As[buf][kk][ty * 16 + 8];
            *(ulonglong2*)(avp + 6) = *(const ulonglong2*)&As[buf][kk][ty * 16 + 12];
            *(ulonglong2*)(bvp + 0) = *(const ulonglong2*)&Bs[buf][kk][tx * 8 + 0];
            *(ulonglong2*)(bvp + 2) = *(const ulonglong2*)&Bs[buf][kk][tx * 8 + 4];
#pragma unroll
            for (int i = 0; i < 8; i++)
#pragma unroll
                for (int j = 0; j < 4; j++)
                    asm("fma.rn.f32x2 %0, %1, %2, %0;"
                        : "+l"(accp[i][j]) : "l"(avp[i]), "l"(bvp[j]));
        }
        if (t + 1 < nk) {
            int nb = buf ^ 1;
            *(float2*)&As[nb][ac4 + 0][2 * arow] = make_float2(a0.x, a0.x);
            *(float2*)&As[nb][ac4 + 1][2 * arow] = make_float2(a0.y, a0.y);
            *(float2*)&As[nb][ac4 + 2][2 * arow] = make_float2(a0.z, a0.z);
            *(float2*)&As[nb][ac4 + 3][2 * arow] = make_float2(a0.w, a0.w);
            *(float2*)&As[nb][ac4 + 0][2 * (arow + 64)] = make_float2(a1.x, a1.x);
            *(float2*)&As[nb][ac4 + 1][2 * (arow + 64)] = make_float2(a1.y, a1.y);
            *(float2*)&As[nb][ac4 + 2][2 * (arow + 64)] = make_float2(a1.z, a1.z);
            *(float2*)&As[nb][ac4 + 3][2 * (arow + 64)] = make_float2(a1.w, a1.w);
            *(float4*)&Bs[nb][brow][bc4]     = b0;
            *(float4*)&Bs[nb][brow + 8][bc4] = b1;
            __syncthreads();
            buf = nb;
        }
    }

    float* Co = Cp + (size_t)blockIdx.z * M * N;
#pragma unroll
    for (int i = 0; i < 8; i++) {
        ulonglong2 v0 = make_ulonglong2(accp[i][0], accp[i][1]);
        ulonglong2 v1 = make_ulonglong2(accp[i][2], accp[i][3]);
        *(ulonglong2*)(Co + (size_t)(m0 + ty * 8 + i) * N + n0 + tx * 8)     = v0;
        *(ulonglong2*)(Co + (size_t)(m0 + ty * 8 + i) * N + n0 + tx * 8 + 4) = v1;
    }
}

// ---------------- init LayerNorm: cs = LN(C0 + b_init) * g + beta; also idx init ----------------
__global__ void init_ln_k(const float* __restrict__ b, const float* __restrict__ g,
                          const float* __restrict__ beta)
{
    int row = blockIdx.x;           // 0..8191 == n*64+s
    int tid = threadIdx.x;          // 128
    __shared__ float sv[512];
    __shared__ float red[128];
    const float* src = d_C0 + (size_t)row * 512;
    for (int d = tid; d < 512; d += 128) sv[d] = src[d] + b[d];
    __syncthreads();
    float p = sv[tid] + sv[tid + 128] + sv[tid + 256] + sv[tid + 384];
    red[tid] = p; __syncthreads();
    for (int off = 64; off > 0; off >>= 1) {
        if (tid < off) red[tid] += red[tid + off];
        __syncthreads();
    }
    float mean = red[0] * (1.0f / 512.0f);
    __syncthreads();
    float q = 0.0f;
    for (int d = tid; d < 512; d += 128) { float x = sv[d] - mean; q += x * x; }
    red[tid] = q; __syncthreads();
    for (int off = 64; off > 0; off >>= 1) {
        if (tid < off) red[tid] += red[tid + off];
        __syncthreads();
    }
    float inv = 1.0f / sqrtf(red[0] * (1.0f / 512.0f) + 1e-5f);
    float* dst = d_cs + (size_t)row * 512;
    for (int d = tid; d < 512; d += 128) dst[d] = (sv[d] - mean) * inv * g[d] + beta[d];
    if (tid == 0) d_idx[row] = row & 63;
}

// ---------------- fused scorer + argmax + compaction + xcat gather ----------------
// One block of 256 threads per batch row. 8 warps score pairs; parallel
// first-max argmax via monotone 64-bit keys; parallel list compaction.
__global__ __launch_bounds__(256) void select_k(
    const float* __restrict__ Wd1, const float* __restrict__ bd1,
    const float* __restrict__ Wd2, const float* __restrict__ bd2,
    const float* __restrict__ mask, int it, int P, int force0)
{
    int n = blockIdx.x;
    int tid = threadIdx.x, w = tid >> 5, lane = tid & 31;
    __shared__ float Wd1s[128 * 64];
    __shared__ float Wd2s[64];
    __shared__ float bd1s[64];
    __shared__ float fs[8][128];
    __shared__ float lg[64];
    __shared__ unsigned long long wmax[8];
    __shared__ int shk[4];   // k, sL, sR, flag

    // preload successor index BEFORE any compaction writes
    int mynext = (tid < 63) ? d_idx[n * 64 + tid + 1] : 0;

    if (!force0) {
        for (int t = tid; t < 128 * 64; t += 256) Wd1s[t] = Wd1[t];
        if (tid < 64) { Wd2s[tid] = Wd2[tid]; bd1s[tid] = bd1[tid]; }
        __syncthreads();
        for (int j = w; j < P; j += 8) {
            int a  = d_idx[n * 64 + j];
            int bs = d_idx[n * 64 + j + 1];
            const float* lrow = d_cs + (size_t)(n * 64 + a) * 512;
            const float* rrow = d_cs + (size_t)(n * 64 + bs) * 512;
            for (int t = lane; t < 128; t += 32)
                fs[w][t] = (t < 64) ? lrow[t] : rrow[t - 64];
            __syncwarp();
            float acc0 = 0.0f, acc1 = 0.0f;
#pragma unroll 16
            for (int k = 0; k < 128; k++) {
                float f = fs[w][k];
                acc0 = fmaf(f, Wd1s[k * 64 + lane], acc0);
                acc1 = fmaf(f, Wd1s[k * 64 + lane + 32], acc1);
            }
            float h0 = gelu_f(acc0 + bd1s[lane]);
            float h1 = gelu_f(acc1 + bd1s[lane + 32]);
            float part = h0 * Wd2s[lane] + h1 * Wd2s[lane + 32];
#pragma unroll
            for (int off = 16; off > 0; off >>= 1)
                part += __shfl_xor_sync(0xffffffffu, part, off);
            if (lane == 0) {
                float mv = mask[n * 64 + it + 1 + j];
                lg[j] = (mv > 0.0f) ? (part + bd2[0]) : -1e9f;
            }
            __syncwarp();  // protect fs[w] before next pair
        }
        __syncthreads();
    }

    // parallel argmax with first-index tie-break: key = (ordered(v) << 32) | (63 - j)
    unsigned long long key = 0ull;
    if (!force0 && tid < P) {
        unsigned u = __float_as_uint(lg[tid]);
        u = (u & 0x80000000u) ? ~u : (u | 0x80000000u);
        key = ((unsigned long long)u << 32) | (unsigned)(63 - tid);
    }
#pragma unroll
    for (int off = 16; off > 0; off >>= 1) {
        unsigned long long o = __shfl_xor_sync(0xffffffffu, key, off);
        if (o > key) key = o;
    }
    if (lane == 0) wmax[w] = key;
    __syncthreads();

    if (tid == 0) {
        unsigned long long best = wmax[0];
#pragma unroll
        for (int i = 1; i < 8; i++) if (wmax[i] > best) best = wmax[i];
        int k = force0 ? 0 : (63 - (int)(best & 0xFFFFFFFFu));
        float done = mask[n * 64 + it + 1];
        int sL = d_idx[n * 64 + k];
        int sR = d_idx[n * 64 + k + 1];
        int fl = (done > 0.0f) ? 1 : 0;
        if (!fl) { sL = d_idx[n * 64]; sR = d_idx[n * 64 + 1]; }
        shk[0] = k; shk[1] = sL; shk[2] = sR; shk[3] = fl;
        d_slotL[n] = sL; d_flag[n] = fl;
    }
    __syncthreads();

    // parallel compaction: idx[j] = idx[j+1] for j in [k+1, P-1]
    if (shk[3] && tid >= shk[0] + 1 && tid <= P - 1)
        d_idx[n * 64 + tid] = mynext;

    // gather xcat = [cs[sL], cs[sR]]
    int sL = shk[1], sR = shk[2];
    const float* lrow = d_cs + (size_t)(n * 64 + sL) * 512;
    const float* rrow = d_cs + (size_t)(n * 64 + sR) * 512;
    float* x = d_xcat + (size_t)n * 1024;
    for (int t = tid; t < 512; t += 256) {
        x[t] = lrow[t];
        x[512 + t] = rrow[t];
    }
}

// ---------------- fc1 split-K reduce + bias + gelu ----------------
__global__ void fc1red_k(const float* __restrict__ b1)
{
    int id = blockIdx.x * 256 + threadIdx.x;   // < 128*2048
    float s = 0.0f;
#pragma unroll
    for (int z = 0; z < SPLITK; z++) s += d_part[(size_t)z * (NB * CHD) + id];
    d_h[id] = gelu_f(s + b1[id & 2047]);
}

// ---------------- fc2 reduce + gates + LayerNorm + write back into cs ----------------
__global__ void gateln_k(const float* __restrict__ b2, const float* __restrict__ g,
                         const float* __restrict__ beta, const float* __restrict__ unused)
{
    int n = blockIdx.x;
    if (d_flag[n] == 0) return;
    int tid = threadIdx.x;   // 256
    __shared__ float sv[512];
    __shared__ float red[256];
    const float* base = d_part + (size_t)n * 2048;
    for (int d = tid; d < 512; d += 256) {
        float c0 = 0.0f, c1 = 0.0f, c2 = 0.0f, c3 = 0.0f;
#pragma unroll
        for (int z = 0; z < SPLITK; z++) {
            const float* pp = base + (size_t)z * (NB * CHD);
            c0 += pp[d]; c1 += pp[512 + d]; c2 += pp[1024 + d]; c3 += pp[1536 + d];
        }
        c0 += b2[d]; c1 += b2[512 + d]; c2 += b2[1024 + d]; c3 += b2[1536 + d];
        float l = d_xcat[(size_t)n * 1024 + d];
        float r = d_xcat[(size_t)n * 1024 + 512 + d];
        sv[d] = sigm_f(c0) * l + sigm_f(c1) * r + sigm_f(c2) * c3;
    }
    __syncthreads();
    float p = sv[tid] + sv[tid + 256];
    red[tid] = p; __syncthreads();
    for (int off = 128; off > 0; off >>= 1) {
        if (tid < off) red[tid] += red[tid + off];
        __syncthreads();
    }
    float mean = red[0] * (1.0f / 512.0f);
    __syncthreads();
    float d0 = sv[tid] - mean, d1 = sv[tid + 256] - mean;
    red[tid] = d0 * d0 + d1 * d1; __syncthreads();
    for (int off = 128; off > 0; off >>= 1) {
        if (tid < off) red[tid] += red[tid + off];
        __syncthreads();
    }
    float inv = 1.0f / sqrtf(red[0] * (1.0f / 512.0f) + 1e-5f);
    float* dst = d_cs + (size_t)(n * 64 + d_slotL[n]) * 512;
    for (int d = tid; d < 512; d += 256)
        dst[d] = (sv[d] - mean) * inv * g[d] + beta[d];
}

// ---------------- final gather: out[n] = cs[n, idx[n][0]] ----------------
__global__ void gather_k(float* __restrict__ out)
{
    int n = blockIdx.x;
    int s0 = d_idx[n * 64];
    const float* src = d_cs + (size_t)(n * 64 + s0) * 512;
    for (int d = threadIdx.x; d < 512; d += 256)
        out[(size_t)n * 512 + d] = src[d];
}

// ---------------- host launcher (graph-capturable: kernel launches only) ----------------
extern "C" void kernel_launch(void* const* d_in, const int* in_sizes, int n_in,
                              void* d_out, int out_size)
{
    const float* input     = (const float*)d_in[0];
    const float* mask      = (const float*)d_in[1];
    const float* W_init    = (const float*)d_in[2];
    const float* b_init    = (const float*)d_in[3];
    const float* g_init    = (const float*)d_in[4];
    const float* beta_init = (const float*)d_in[5];
    const float* W_d1      = (const float*)d_in[6];
    const float* b_d1      = (const float*)d_in[7];
    const float* W_d2      = (const float*)d_in[8];
    const float* b_d2      = (const float*)d_in[9];
    const float* W_c1      = (const float*)d_in[10];
    const float* b_c1      = (const float*)d_in[11];
    const float* W_c2      = (const float*)d_in[12];
    const float* b_c2      = (const float*)d_in[13];
    const float* g_c       = (const float*)d_in[14];
    const float* beta_c    = (const float*)d_in[15];

    float *p_C0, *p_part, *p_h, *p_xcat;
    cudaGetSymbolAddress((void**)&p_C0,   d_C0);
    cudaGetSymbolAddress((void**)&p_part, d_part);
    cudaGetSymbolAddress((void**)&p_h,    d_h);
    cudaGetSymbolAddress((void**)&p_xcat, d_xcat);

    // init: cs = LN(input @ W_init + b_init)
    sgemm_k<<<dim3(4, 64, 1), 256>>>(input, W_init, p_C0, 8192, 512, 512, 512);
    init_ln_k<<<8192, 128>>>(b_init, g_init, beta_init);

    for (int i = 0; i < 63; i++) {
        int Scur = 64 - i;
        int P = Scur - 1;
        select_k<<<NB, 256>>>(W_d1, b_d1, W_d2, b_d2, mask, i, P, (i == 62) ? 1 : 0);
        // fc1: xcat(128x1024) @ W_c1(1024x2048), split-K=16 (chunks of 64)
        sgemm_k<<<dim3(16, 1, SPLITK), 256>>>(p_xcat, W_c1, p_part, 128, 2048, 1024, 64);
        fc1red_k<<<(NB * CHD) / 256, 256>>>(b_c1);
        // fc2: h(128x2048) @ W_c2(2048x2048), split-K=16 (chunks of 128)
        sgemm_k<<<dim3(16, 1, SPLITK), 256>>>(p_h, W_c2, p_part, 128, 2048, 2048, 128);
        gateln_k<<<NB, 256>>>(b_c2, g_c, beta_c, 0);
    }
    gather_k<<<NB, 256>>>((float*)d_out);
}

// round 4
// speedup vs baseline: 1.2193x; 1.2193x over previous
#include <cuda_runtime.h>
#include <math.h>

// Problem constants
#define NB 128      // batch
#define SS 64       // initial sequence length
#define DD 512      // model dim
#define CHD 2048    // hidden dim of GRC fc1 / per-group width of fc2 output
#define SPLITK 16

// ---------------- device scratch (no allocations allowed) ----------------
__device__ float d_cs[NB * SS * DD];        // chart states, slot-addressed
__device__ float d_C0[NB * SS * DD];        // init GEMM output
__device__ float d_part[SPLITK * NB * CHD]; // split-K partial sums (shared fc1/fc2)
__device__ float d_h[NB * CHD];             // fc1 activations
__device__ float d_xcat[NB * 1024];         // [l, r] concat for selected pairs
__device__ int   d_idx[NB * SS];            // active slot list per row
__device__ int   d_slotL[NB];
__device__ int   d_flag[NB];

__device__ __forceinline__ float gelu_f(float x) {
    float x3 = x * x * x;
    return 0.5f * x * (1.0f + tanhf(0.7978845608028654f * (x + 0.044715f * x3)));
}
__device__ __forceinline__ float sigm_f(float x) {
    return 1.0f / (1.0f + expf(-x));
}

// ---------------- fp32 SGEMM, double-buffered, packed f32x2 math ----------------
// A: MxK row-major, B: KxN row-major. Block tile 128x128, 8x8 per thread,
// deterministic split-K via blockIdx.z writing disjoint partial buffers.
// Smem layout identical to the round-2 scalar version (4x LDS.128 per k-step).
// The broadcast A operand is packed in REGISTERS (mov.b64 {a,a}) so the inner
// loop runs 32 fma.rn.f32x2 instead of 64 scalar FFMA, at unchanged smem
// traffic. Each packed half rounds exactly like scalar FFMA -> bit-identical.
__global__ __launch_bounds__(256, 2) void sgemm_k(
    const float* __restrict__ A, const float* __restrict__ B, float* __restrict__ Cp,
    int M, int N, int K, int kc)
{
    __shared__ __align__(16) float As[2][16][128];
    __shared__ __align__(16) float Bs[2][16][128];
    const int tid = threadIdx.x;
    const int tx = tid & 15;
    const int ty = tid >> 4;
    const int m0 = blockIdx.y * 128;
    const int n0 = blockIdx.x * 128;
    const int k0 = blockIdx.z * kc;
    const int nk = kc >> 4;

    unsigned long long accp[8][4];   // 8 rows x 4 packed column-pairs
#pragma unroll
    for (int i = 0; i < 8; i++)
#pragma unroll
        for (int j = 0; j < 4; j++) accp[i][j] = 0ull;

    const int arow = tid >> 2;          // 0..63
    const int ac4  = (tid & 3) << 2;    // 0,4,8,12
    const int brow = tid >> 5;          // 0..7
    const int bc4  = (tid & 31) << 2;   // 0..124

    const float* Ap = A + (size_t)(m0 + arow) * K + k0 + ac4;
    const float* Bp = B + (size_t)(k0 + brow) * N + n0 + bc4;

    // prologue: load tile 0
    float4 a0 = *(const float4*)(Ap);
    float4 a1 = *(const float4*)(Ap + (size_t)64 * K);
    float4 b0 = *(const float4*)(Bp);
    float4 b1 = *(const float4*)(Bp + (size_t)8 * N);
    As[0][ac4 + 0][arow] = a0.x; As[0][ac4 + 1][arow] = a0.y;
    As[0][ac4 + 2][arow] = a0.z; As[0][ac4 + 3][arow] = a0.w;
    As[0][ac4 + 0][arow + 64] = a1.x; As[0][ac4 + 1][arow + 64] = a1.y;
    As[0][ac4 + 2][arow + 64] = a1.z; As[0][ac4 + 3][arow + 64] = a1.w;
    *(float4*)&Bs[0][brow][bc4]     = b0;
    *(float4*)&Bs[0][brow + 8][bc4] = b1;
    __syncthreads();

    int buf = 0;
    for (int t = 0; t < nk; t++) {
        if (t + 1 < nk) {   // prefetch next tile into registers (overlaps compute)
            const float* Apn = Ap + (t + 1) * 16;
            const float* Bpn = Bp + (size_t)(t + 1) * 16 * N;
            a0 = *(const float4*)(Apn);
            a1 = *(const float4*)(Apn + (size_t)64 * K);
            b0 = *(const float4*)(Bpn);
            b1 = *(const float4*)(Bpn + (size_t)8 * N);
        }
#pragma unroll
        for (int kk = 0; kk < 16; kk++) {
            float av[8];
            unsigned long long avp[8], bvp[4];
            *(float4*)(av)     = *(const float4*)&As[buf][kk][ty * 8];
            *(float4*)(av + 4) = *(const float4*)&As[buf][kk][ty * 8 + 4];
            *(ulonglong2*)(bvp + 0) = *(const ulonglong2*)&Bs[buf][kk][tx * 8 + 0];
            *(ulonglong2*)(bvp + 2) = *(const ulonglong2*)&Bs[buf][kk][tx * 8 + 4];
#pragma unroll
            for (int i = 0; i < 8; i++)
                asm("mov.b64 %0, {%1, %1};" : "=l"(avp[i]) : "f"(av[i]));
#pragma unroll
            for (int i = 0; i < 8; i++)
#pragma unroll
                for (int j = 0; j < 4; j++)
                    asm("fma.rn.f32x2 %0, %1, %2, %0;"
                        : "+l"(accp[i][j]) : "l"(avp[i]), "l"(bvp[j]));
        }
        if (t + 1 < nk) {
            int nb = buf ^ 1;
            As[nb][ac4 + 0][arow] = a0.x; As[nb][ac4 + 1][arow] = a0.y;
            As[nb][ac4 + 2][arow] = a0.z; As[nb][ac4 + 3][arow] = a0.w;
            As[nb][ac4 + 0][arow + 64] = a1.x; As[nb][ac4 + 1][arow + 64] = a1.y;
            As[nb][ac4 + 2][arow + 64] = a1.z; As[nb][ac4 + 3][arow + 64] = a1.w;
            *(float4*)&Bs[nb][brow][bc4]     = b0;
            *(float4*)&Bs[nb][brow + 8][bc4] = b1;
            __syncthreads();
            buf = nb;
        }
    }

    float* Co = Cp + (size_t)blockIdx.z * M * N;
#pragma unroll
    for (int i = 0; i < 8; i++) {
        ulonglong2 v0 = make_ulonglong2(accp[i][0], accp[i][1]);
        ulonglong2 v1 = make_ulonglong2(accp[i][2], accp[i][3]);
        *(ulonglong2*)(Co + (size_t)(m0 + ty * 8 + i) * N + n0 + tx * 8)     = v0;
        *(ulonglong2*)(Co + (size_t)(m0 + ty * 8 + i) * N + n0 + tx * 8 + 4) = v1;
    }
}

// ---------------- init LayerNorm: cs = LN(C0 + b_init) * g + beta; also idx init ----------------
__global__ void init_ln_k(const float* __restrict__ b, const float* __restrict__ g,
                          const float* __restrict__ beta)
{
    int row = blockIdx.x;           // 0..8191 == n*64+s
    int tid = threadIdx.x;          // 128
    __shared__ float sv[512];
    __shared__ float red[128];
    const float* src = d_C0 + (size_t)row * 512;
    for (int d = tid; d < 512; d += 128) sv[d] = src[d] + b[d];
    __syncthreads();
    float p = sv[tid] + sv[tid + 128] + sv[tid + 256] + sv[tid + 384];
    red[tid] = p; __syncthreads();
    for (int off = 64; off > 0; off >>= 1) {
        if (tid < off) red[tid] += red[tid + off];
        __syncthreads();
    }
    float mean = red[0] * (1.0f / 512.0f);
    __syncthreads();
    float q = 0.0f;
    for (int d = tid; d < 512; d += 128) { float x = sv[d] - mean; q += x * x; }
    red[tid] = q; __syncthreads();
    for (int off = 64; off > 0; off >>= 1) {
        if (tid < off) red[tid] += red[tid + off];
        __syncthreads();
    }
    float inv = 1.0f / sqrtf(red[0] * (1.0f / 512.0f) + 1e-5f);
    float* dst = d_cs + (size_t)row * 512;
    for (int d = tid; d < 512; d += 128) dst[d] = (sv[d] - mean) * inv * g[d] + beta[d];
    if (tid == 0) d_idx[row] = row & 63;
}

// ---------------- fused (prev-iter gate+LN) + scorer + argmax + compaction + gather ----------------
// One block of 256 threads per batch row. If do_ln, first finish the previous
// iteration's GRC output (fc2 split-K reduce + gates + LayerNorm -> cs[sL]).
// Then: 8 warps score pairs; parallel first-max argmax; parallel compaction;
// gather xcat for this iteration's GRC.
__global__ __launch_bounds__(256) void select_k(
    const float* __restrict__ Wd1, const float* __restrict__ bd1,
    const float* __restrict__ Wd2, const float* __restrict__ bd2,
    const float* __restrict__ mask,
    const float* __restrict__ b2, const float* __restrict__ g,
    const float* __restrict__ beta,
    int it, int P, int force0, int do_ln)
{
    int n = blockIdx.x;
    int tid = threadIdx.x, w = tid >> 5, lane = tid & 31;
    __shared__ float Wd1s[128 * 64];
    __shared__ float Wd2s[64];
    __shared__ float bd1s[64];
    __shared__ float fs[8][128];
    __shared__ float lg[64];
    __shared__ float sv[512];
    __shared__ float red[256];
    __shared__ unsigned long long wmax[8];
    __shared__ int shk[4];   // k, sL, sR, flag

    // ---- phase 0: previous iteration's gate + LayerNorm ----
    if (do_ln && d_flag[n] != 0) {
        const float* base = d_part + (size_t)n * 2048;
        for (int d = tid; d < 512; d += 256) {
            float c0 = 0.0f, c1 = 0.0f, c2 = 0.0f, c3 = 0.0f;
#pragma unroll
            for (int z = 0; z < SPLITK; z++) {
                const float* pp = base + (size_t)z * (NB * CHD);
                c0 += pp[d]; c1 += pp[512 + d]; c2 += pp[1024 + d]; c3 += pp[1536 + d];
            }
            c0 += b2[d]; c1 += b2[512 + d]; c2 += b2[1024 + d]; c3 += b2[1536 + d];
            float l = d_xcat[(size_t)n * 1024 + d];
            float r = d_xcat[(size_t)n * 1024 + 512 + d];
            sv[d] = sigm_f(c0) * l + sigm_f(c1) * r + sigm_f(c2) * c3;
        }
        __syncthreads();
        float p = sv[tid] + sv[tid + 256];
        red[tid] = p; __syncthreads();
        for (int off = 128; off > 0; off >>= 1) {
            if (tid < off) red[tid] += red[tid + off];
            __syncthreads();
        }
        float mean = red[0] * (1.0f / 512.0f);
        __syncthreads();
        float d0 = sv[tid] - mean, d1 = sv[tid + 256] - mean;
        red[tid] = d0 * d0 + d1 * d1; __syncthreads();
        for (int off = 128; off > 0; off >>= 1) {
            if (tid < off) red[tid] += red[tid + off];
            __syncthreads();
        }
        float inv = 1.0f / sqrtf(red[0] * (1.0f / 512.0f) + 1e-5f);
        float* dst = d_cs + (size_t)(n * 64 + d_slotL[n]) * 512;
        for (int d = tid; d < 512; d += 256)
            dst[d] = (sv[d] - mean) * inv * g[d] + beta[d];
        __syncthreads();
    }

    // preload successor index BEFORE any compaction writes
    int mynext = (tid < 63) ? d_idx[n * 64 + tid + 1] : 0;

    // ---- phase 1: scorer ----
    if (!force0) {
        for (int t = tid; t < 128 * 64; t += 256) Wd1s[t] = Wd1[t];
        if (tid < 64) { Wd2s[tid] = Wd2[tid]; bd1s[tid] = bd1[tid]; }
        __syncthreads();
        for (int j = w; j < P; j += 8) {
            int a  = d_idx[n * 64 + j];
            int bs = d_idx[n * 64 + j + 1];
            const float* lrow = d_cs + (size_t)(n * 64 + a) * 512;
            const float* rrow = d_cs + (size_t)(n * 64 + bs) * 512;
            for (int t = lane; t < 128; t += 32)
                fs[w][t] = (t < 64) ? lrow[t] : rrow[t - 64];
            __syncwarp();
            float acc0 = 0.0f, acc1 = 0.0f;
#pragma unroll 16
            for (int k = 0; k < 128; k++) {
                float f = fs[w][k];
                acc0 = fmaf(f, Wd1s[k * 64 + lane], acc0);
                acc1 = fmaf(f, Wd1s[k * 64 + lane + 32], acc1);
            }
            float h0 = gelu_f(acc0 + bd1s[lane]);
            float h1 = gelu_f(acc1 + bd1s[lane + 32]);
            float part = h0 * Wd2s[lane] + h1 * Wd2s[lane + 32];
#pragma unroll
            for (int off = 16; off > 0; off >>= 1)
                part += __shfl_xor_sync(0xffffffffu, part, off);
            if (lane == 0) {
                float mv = mask[n * 64 + it + 1 + j];
                lg[j] = (mv > 0.0f) ? (part + bd2[0]) : -1e9f;
            }
            __syncwarp();  // protect fs[w] before next pair
        }
        __syncthreads();
    }

    // ---- phase 2: argmax with first-index tie-break ----
    unsigned long long key = 0ull;
    if (!force0 && tid < P) {
        unsigned u = __float_as_uint(lg[tid]);
        u = (u & 0x80000000u) ? ~u : (u | 0x80000000u);
        key = ((unsigned long long)u << 32) | (unsigned)(63 - tid);
    }
#pragma unroll
    for (int off = 16; off > 0; off >>= 1) {
        unsigned long long o = __shfl_xor_sync(0xffffffffu, key, off);
        if (o > key) key = o;
    }
    if (lane == 0) wmax[w] = key;
    __syncthreads();

    if (tid == 0) {
        unsigned long long best = wmax[0];
#pragma unroll
        for (int i = 1; i < 8; i++) if (wmax[i] > best) best = wmax[i];
        int k = force0 ? 0 : (63 - (int)(best & 0xFFFFFFFFu));
        float done = mask[n * 64 + it + 1];
        int sL = d_idx[n * 64 + k];
        int sR = d_idx[n * 64 + k + 1];
        int fl = (done > 0.0f) ? 1 : 0;
        if (!fl) { sL = d_idx[n * 64]; sR = d_idx[n * 64 + 1]; }
        shk[0] = k; shk[1] = sL; shk[2] = sR; shk[3] = fl;
        d_slotL[n] = sL; d_flag[n] = fl;
    }
    __syncthreads();

    // ---- phase 3: compaction + xcat gather ----
    if (shk[3] && tid >= shk[0] + 1 && tid <= P - 1)
        d_idx[n * 64 + tid] = mynext;

    int sL = shk[1], sR = shk[2];
    const float* lrow = d_cs + (size_t)(n * 64 + sL) * 512;
    const float* rrow = d_cs + (size_t)(n * 64 + sR) * 512;
    float* x = d_xcat + (size_t)n * 1024;
    for (int t = tid; t < 512; t += 256) {
        x[t] = lrow[t];
        x[512 + t] = rrow[t];
    }
}

// ---------------- fc1 split-K reduce + bias + gelu ----------------
__global__ void fc1red_k(const float* __restrict__ b1)
{
    int id = blockIdx.x * 256 + threadIdx.x;   // < 128*2048
    float s = 0.0f;
#pragma unroll
    for (int z = 0; z < SPLITK; z++) s += d_part[(size_t)z * (NB * CHD) + id];
    d_h[id] = gelu_f(s + b1[id & 2047]);
}

// ---------------- final fc2 reduce + gates + LayerNorm (last iteration only) ----------------
__global__ void gateln_k(const float* __restrict__ b2, const float* __restrict__ g,
                         const float* __restrict__ beta)
{
    int n = blockIdx.x;
    if (d_flag[n] == 0) return;
    int tid = threadIdx.x;   // 256
    __shared__ float sv[512];
    __shared__ float red[256];
    const float* base = d_part + (size_t)n * 2048;
    for (int d = tid; d < 512; d += 256) {
        float c0 = 0.0f, c1 = 0.0f, c2 = 0.0f, c3 = 0.0f;
#pragma unroll
        for (int z = 0; z < SPLITK; z++) {
            const float* pp = base + (size_t)z * (NB * CHD);
            c0 += pp[d]; c1 += pp[512 + d]; c2 += pp[1024 + d]; c3 += pp[1536 + d];
        }
        c0 += b2[d]; c1 += b2[512 + d]; c2 += b2[1024 + d]; c3 += b2[1536 + d];
        float l = d_xcat[(size_t)n * 1024 + d];
        float r = d_xcat[(size_t)n * 1024 + 512 + d];
        sv[d] = sigm_f(c0) * l + sigm_f(c1) * r + sigm_f(c2) * c3;
    }
    __syncthreads();
    float p = sv[tid] + sv[tid + 256];
    red[tid] = p; __syncthreads();
    for (int off = 128; off > 0; off >>= 1) {
        if (tid < off) red[tid] += red[tid + off];
        __syncthreads();
    }
    float mean = red[0] * (1.0f / 512.0f);
    __syncthreads();
    float d0 = sv[tid] - mean, d1 = sv[tid + 256] - mean;
    red[tid] = d0 * d0 + d1 * d1; __syncthreads();
    for (int off = 128; off > 0; off >>= 1) {
        if (tid < off) red[tid] += red[tid + off];
        __syncthreads();
    }
    float inv = 1.0f / sqrtf(red[0] * (1.0f / 512.0f) + 1e-5f);
    float* dst = d_cs + (size_t)(n * 64 + d_slotL[n]) * 512;
    for (int d = tid; d < 512; d += 256)
        dst[d] = (sv[d] - mean) * inv * g[d] + beta[d];
}

// ---------------- final gather: out[n] = cs[n, idx[n][0]] ----------------
__global__ void gather_k(float* __restrict__ out)
{
    int n = blockIdx.x;
    int s0 = d_idx[n * 64];
    const float* src = d_cs + (size_t)(n * 64 + s0) * 512;
    for (int d = threadIdx.x; d < 512; d += 256)
        out[(size_t)n * 512 + d] = src[d];
}

// ---------------- host launcher (graph-capturable: kernel launches only) ----------------
extern "C" void kernel_launch(void* const* d_in, const int* in_sizes, int n_in,
                              void* d_out, int out_size)
{
    const float* input     = (const float*)d_in[0];
    const float* mask      = (const float*)d_in[1];
    const float* W_init    = (const float*)d_in[2];
    const float* b_init    = (const float*)d_in[3];
    const float* g_init    = (const float*)d_in[4];
    const float* beta_init = (const float*)d_in[5];
    const float* W_d1      = (const float*)d_in[6];
    const float* b_d1      = (const float*)d_in[7];
    const float* W_d2      = (const float*)d_in[8];
    const float* b_d2      = (const float*)d_in[9];
    const float* W_c1      = (const float*)d_in[10];
    const float* b_c1      = (const float*)d_in[11];
    const float* W_c2      = (const float*)d_in[12];
    const float* b_c2      = (const float*)d_in[13];
    const float* g_c       = (const float*)d_in[14];
    const float* beta_c    = (const float*)d_in[15];

    float *p_C0, *p_part, *p_h, *p_xcat;
    cudaGetSymbolAddress((void**)&p_C0,   d_C0);
    cudaGetSymbolAddress((void**)&p_part, d_part);
    cudaGetSymbolAddress((void**)&p_h,    d_h);
    cudaGetSymbolAddress((void**)&p_xcat, d_xcat);

    // init: cs = LN(input @ W_init + b_init)
    sgemm_k<<<dim3(4, 64, 1), 256>>>(input, W_init, p_C0, 8192, 512, 512, 512);
    init_ln_k<<<8192, 128>>>(b_init, g_init, beta_init);

    for (int i = 0; i < 63; i++) {
        int Scur = 64 - i;
        int P = Scur - 1;
        // select also completes iteration i-1's gate+LN (do_ln = i>0)
        select_k<<<NB, 256>>>(W_d1, b_d1, W_d2, b_d2, mask,
                              b_c2, g_c, beta_c,
                              i, P, (i == 62) ? 1 : 0, (i > 0) ? 1 : 0);
        // fc1: xcat(128x1024) @ W_c1(1024x2048), split-K=16 (chunks of 64)
        sgemm_k<<<dim3(16, 1, SPLITK), 256>>>(p_xcat, W_c1, p_part, 128, 2048, 1024, 64);
        fc1red_k<<<(NB * CHD) / 256, 256>>>(b_c1);
        // fc2: h(128x2048) @ W_c2(2048x2048), split-K=16 (chunks of 128)
        sgemm_k<<<dim3(16, 1, SPLITK), 256>>>(p_h, W_c2, p_part, 128, 2048, 2048, 128);
    }
    gateln_k<<<NB, 256>>>(b_c2, g_c, beta_c);   // last iteration's gate+LN
    gather_k<<<NB, 256>>>((float*)d_out);
}

// round 9
// speedup vs baseline: 1.2277x; 1.0069x over previous
#include <cuda_runtime.h>
#include <math.h>

// Problem constants
#define NB 128      // batch
#define SS 64       // initial sequence length
#define DD 512      // model dim
#define CHD 2048    // hidden dim of GRC fc1 / per-group width of fc2 output
#define SPLITK1 8   // fc1 split-K
#define SPLITK2 16  // fc2 split-K

// ---------------- device scratch (no allocations allowed) ----------------
__device__ float d_cs[NB * SS * DD];          // chart states, slot-addressed
__device__ float d_C0[NB * SS * DD];          // init GEMM output
__device__ float d_part[SPLITK2 * NB * CHD];  // split-K partial sums (shared fc1/fc2)
__device__ float d_h[NB * CHD];               // fc1 activations
__device__ float d_xcat[NB * 1024];           // [l, r] concat for selected pairs
__device__ float d_logits[NB * 64];           // cached raw pair logits
__device__ int   d_idx[NB * SS];              // active slot list per row
__device__ int   d_slotL[NB];
__device__ int   d_flag[NB];
__device__ int   d_prevk[NB];
__device__ unsigned int d_cnt1[16];           // fc1 tail-reduce arrival counters

__device__ __forceinline__ float gelu_f(float x) {
    float x3 = x * x * x;
    return 0.5f * x * (1.0f + tanhf(0.7978845608028654f * (x + 0.044715f * x3)));
}
__device__ __forceinline__ float sigm_f(float x) {
    return 1.0f / (1.0f + expf(-x));
}

// ---------------- fp32 SGEMM, double-buffered, packed f32x2 math ----------------
// A: MxK row-major, B: KxN row-major. Block tile 128x128, 8x8 per thread,
// deterministic split-K via blockIdx.z writing disjoint partial buffers.
// Broadcast A operand packed in registers (mov.b64 {a,a}); 32 fma.rn.f32x2
// per k-step, smem traffic = scalar version. Bit-identical per-lane rounding.
__global__ __launch_bounds__(256, 2) void sgemm_k(
    const float* __restrict__ A, const float* __restrict__ B, float* __restrict__ Cp,
    int M, int N, int K, int kc)
{
    __shared__ __align__(16) float As[2][16][128];
    __shared__ __align__(16) float Bs[2][16][128];
    const int tid = threadIdx.x;
    const int tx = tid & 15;
    const int ty = tid >> 4;
    const int m0 = blockIdx.y * 128;
    const int n0 = blockIdx.x * 128;
    const int k0 = blockIdx.z * kc;
    const int nk = kc >> 4;

    unsigned long long accp[8][4];
#pragma unroll
    for (int i = 0; i < 8; i++)
#pragma unroll
        for (int j = 0; j < 4; j++) accp[i][j] = 0ull;

    const int arow = tid >> 2;
    const int ac4  = (tid & 3) << 2;
    const int brow = tid >> 5;
    const int bc4  = (tid & 31) << 2;

    const float* Ap = A + (size_t)(m0 + arow) * K + k0 + ac4;
    const float* Bp = B + (size_t)(k0 + brow) * N + n0 + bc4;

    float4 ta0 = *(const float4*)(Ap);
    float4 ta1 = *(const float4*)(Ap + (size_t)64 * K);
    float4 tb0 = *(const float4*)(Bp);
    float4 tb1 = *(const float4*)(Bp + (size_t)8 * N);
    As[0][ac4 + 0][arow] = ta0.x; As[0][ac4 + 1][arow] = ta0.y;
    As[0][ac4 + 2][arow] = ta0.z; As[0][ac4 + 3][arow] = ta0.w;
    As[0][ac4 + 0][arow + 64] = ta1.x; As[0][ac4 + 1][arow + 64] = ta1.y;
    As[0][ac4 + 2][arow + 64] = ta1.z; As[0][ac4 + 3][arow + 64] = ta1.w;
    *(float4*)&Bs[0][brow][bc4]     = tb0;
    *(float4*)&Bs[0][brow + 8][bc4] = tb1;
    __syncthreads();

    int buf = 0;
    for (int t = 0; t < nk; t++) {
        if (t + 1 < nk) {
            const float* Apn = Ap + (t + 1) * 16;
            const float* Bpn = Bp + (size_t)(t + 1) * 16 * N;
            ta0 = *(const float4*)(Apn);
            ta1 = *(const float4*)(Apn + (size_t)64 * K);
            tb0 = *(const float4*)(Bpn);
            tb1 = *(const float4*)(Bpn + (size_t)8 * N);
        }
#pragma unroll
        for (int kk = 0; kk < 16; kk++) {
            float av[8];
            unsigned long long avp[8], bvp[4];
            *(float4*)(av)     = *(const float4*)&As[buf][kk][ty * 8];
            *(float4*)(av + 4) = *(const float4*)&As[buf][kk][ty * 8 + 4];
            *(ulonglong2*)(bvp + 0) = *(const ulonglong2*)&Bs[buf][kk][tx * 8 + 0];
            *(ulonglong2*)(bvp + 2) = *(const ulonglong2*)&Bs[buf][kk][tx * 8 + 4];
#pragma unroll
            for (int i = 0; i < 8; i++)
                asm("mov.b64 %0, {%1, %1};" : "=l"(avp[i]) : "f"(av[i]));
#pragma unroll
            for (int i = 0; i < 8; i++)
#pragma unroll
                for (int j = 0; j < 4; j++)
                    asm("fma.rn.f32x2 %0, %1, %2, %0;"
                        : "+l"(accp[i][j]) : "l"(avp[i]), "l"(bvp[j]));
        }
        if (t + 1 < nk) {
            int nb = buf ^ 1;
            As[nb][ac4 + 0][arow] = ta0.x; As[nb][ac4 + 1][arow] = ta0.y;
            As[nb][ac4 + 2][arow] = ta0.z; As[nb][ac4 + 3][arow] = ta0.w;
            As[nb][ac4 + 0][arow + 64] = ta1.x; As[nb][ac4 + 1][arow + 64] = ta1.y;
            As[nb][ac4 + 2][arow + 64] = ta1.z; As[nb][ac4 + 3][arow + 64] = ta1.w;
            *(float4*)&Bs[nb][brow][bc4]     = tb0;
            *(float4*)&Bs[nb][brow + 8][bc4] = tb1;
            __syncthreads();
            buf = nb;
        }
    }

    float* Co = Cp + (size_t)blockIdx.z * M * N;
#pragma unroll
    for (int i = 0; i < 8; i++) {
        ulonglong2 v0 = make_ulonglong2(accp[i][0], accp[i][1]);
        ulonglong2 v1 = make_ulonglong2(accp[i][2], accp[i][3]);
        *(ulonglong2*)(Co + (size_t)(m0 + ty * 8 + i) * N + n0 + tx * 8)     = v0;
        *(ulonglong2*)(Co + (size_t)(m0 + ty * 8 + i) * N + n0 + tx * 8 + 4) = v1;
    }
}

// ---------------- fc1 GEMM with fused deterministic split-K tail ----------------
// xcat(128x1024) @ W_c1(1024x2048), grid (16 n-tiles, 1, 8 z). After writing its
// partial, the last-arriving block of each n-tile reduces the 8 partials in fixed
// z order, adds bias, applies gelu, writes d_h. Deterministic: fixed sum order.
__global__ __launch_bounds__(256, 2) void fc1_k(
    const float* __restrict__ B, const float* __restrict__ bias1)
{
    const int M = 128, N = 2048, K = 1024, KC = 128;
    __shared__ __align__(16) float As[2][16][128];
    __shared__ __align__(16) float Bs[2][16][128];
    const int tid = threadIdx.x;
    const int tx = tid & 15;
    const int ty = tid >> 4;
    const int n0 = blockIdx.x * 128;
    const int k0 = blockIdx.z * KC;
    const int nk = KC >> 4;   // 8
    const float* A = d_xcat;

    unsigned long long accp[8][4];
#pragma unroll
    for (int i = 0; i < 8; i++)
#pragma unroll
        for (int j = 0; j < 4; j++) accp[i][j] = 0ull;

    const int arow = tid >> 2;
    const int ac4  = (tid & 3) << 2;
    const int brow = tid >> 5;
    const int bc4  = (tid & 31) << 2;

    const float* Ap = A + (size_t)arow * K + k0 + ac4;
    const float* Bp = B + (size_t)(k0 + brow) * N + n0 + bc4;

    float4 ta0 = *(const float4*)(Ap);
    float4 ta1 = *(const float4*)(Ap + (size_t)64 * K);
    float4 tb0 = *(const float4*)(Bp);
    float4 tb1 = *(const float4*)(Bp + (size_t)8 * N);
    As[0][ac4 + 0][arow] = ta0.x; As[0][ac4 + 1][arow] = ta0.y;
    As[0][ac4 + 2][arow] = ta0.z; As[0][ac4 + 3][arow] = ta0.w;
    As[0][ac4 + 0][arow + 64] = ta1.x; As[0][ac4 + 1][arow + 64] = ta1.y;
    As[0][ac4 + 2][arow + 64] = ta1.z; As[0][ac4 + 3][arow + 64] = ta1.w;
    *(float4*)&Bs[0][brow][bc4]     = tb0;
    *(float4*)&Bs[0][brow + 8][bc4] = tb1;
    __syncthreads();

    int buf = 0;
    for (int t = 0; t < nk; t++) {
        if (t + 1 < nk) {
            const float* Apn = Ap + (t + 1) * 16;
            const float* Bpn = Bp + (size_t)(t + 1) * 16 * N;
            ta0 = *(const float4*)(Apn);
            ta1 = *(const float4*)(Apn + (size_t)64 * K);
            tb0 = *(const float4*)(Bpn);
            tb1 = *(const float4*)(Bpn + (size_t)8 * N);
        }
#pragma unroll
        for (int kk = 0; kk < 16; kk++) {
            float av[8];
            unsigned long long avp[8], bvp[4];
            *(float4*)(av)     = *(const float4*)&As[buf][kk][ty * 8];
            *(float4*)(av + 4) = *(const float4*)&As[buf][kk][ty * 8 + 4];
            *(ulonglong2*)(bvp + 0) = *(const ulonglong2*)&Bs[buf][kk][tx * 8 + 0];
            *(ulonglong2*)(bvp + 2) = *(const ulonglong2*)&Bs[buf][kk][tx * 8 + 4];
#pragma unroll
            for (int i = 0; i < 8; i++)
                asm("mov.b64 %0, {%1, %1};" : "=l"(avp[i]) : "f"(av[i]));
#pragma unroll
            for (int i = 0; i < 8; i++)
#pragma unroll
                for (int j = 0; j < 4; j++)
                    asm("fma.rn.f32x2 %0, %1, %2, %0;"
                        : "+l"(accp[i][j]) : "l"(avp[i]), "l"(bvp[j]));
        }
        if (t + 1 < nk) {
            int nb = buf ^ 1;
            As[nb][ac4 + 0][arow] = ta0.x; As[nb][ac4 + 1][arow] = ta0.y;
            As[nb][ac4 + 2][arow] = ta0.z; As[nb][ac4 + 3][arow] = ta0.w;
            As[nb][ac4 + 0][arow + 64] = ta1.x; As[nb][ac4 + 1][arow + 64] = ta1.y;
            As[nb][ac4 + 2][arow + 64] = ta1.z; As[nb][ac4 + 3][arow + 64] = ta1.w;
            *(float4*)&Bs[nb][brow][bc4]     = tb0;
            *(float4*)&Bs[nb][brow + 8][bc4] = tb1;
            __syncthreads();
            buf = nb;
        }
    }

    float* Co = d_part + (size_t)blockIdx.z * M * N;
#pragma unroll
    for (int i = 0; i < 8; i++) {
        ulonglong2 v0 = make_ulonglong2(accp[i][0], accp[i][1]);
        ulonglong2 v1 = make_ulonglong2(accp[i][2], accp[i][3]);
        *(ulonglong2*)(Co + (size_t)(ty * 8 + i) * N + n0 + tx * 8)     = v0;
        *(ulonglong2*)(Co + (size_t)(ty * 8 + i) * N + n0 + tx * 8 + 4) = v1;
    }

    // ---- fused split-K tail: last block of this n-tile reduces + gelu ----
    __threadfence();
    __syncthreads();
    __shared__ unsigned int s_old;
    if (tid == 0) s_old = atomicAdd(&d_cnt1[blockIdx.x], 1u);
    __syncthreads();
    if (s_old == SPLITK1 - 1) {
        if (tid == 0) d_cnt1[blockIdx.x] = 0;   // reset for next launch
#pragma unroll
        for (int t = 0; t < 16; t++) {
            int i = tid + 256 * t;              // 0..4095 float4 slots
            int row = i >> 5;
            int c4 = (i & 31) << 2;
            size_t off = (size_t)row * 2048 + n0 + c4;
            float4 s = *(const float4*)(d_part + off);
#pragma unroll
            for (int z = 1; z < SPLITK1; z++) {
                float4 p = *(const float4*)(d_part + (size_t)z * (M * N) + off);
                s.x += p.x; s.y += p.y; s.z += p.z; s.w += p.w;
            }
            float4 bb = *(const float4*)(bias1 + n0 + c4);
            s.x = gelu_f(s.x + bb.x); s.y = gelu_f(s.y + bb.y);
            s.z = gelu_f(s.z + bb.z); s.w = gelu_f(s.w + bb.w);
            *(float4*)(d_h + off) = s;
        }
    }
}

// ---------------- init LayerNorm: cs = LN(C0 + b_init) * g + beta; idx init ----------------
__global__ void init_ln_k(const float* __restrict__ b, const float* __restrict__ g,
                          const float* __restrict__ beta)
{
    int row = blockIdx.x;           // 0..8191 == n*64+s
    int tid = threadIdx.x;          // 128
    __shared__ float sv[512];
    __shared__ float red[128];
    const float* src = d_C0 + (size_t)row * 512;
    for (int d = tid; d < 512; d += 128) sv[d] = src[d] + b[d];
    __syncthreads();
    float p = sv[tid] + sv[tid + 128] + sv[tid + 256] + sv[tid + 384];
    red[tid] = p; __syncthreads();
    for (int off = 64; off > 0; off >>= 1) {
        if (tid < off) red[tid] += red[tid + off];
        __syncthreads();
    }
    float mean = red[0] * (1.0f / 512.0f);
    __syncthreads();
    float q = 0.0f;
    for (int d = tid; d < 512; d += 128) { float x = sv[d] - mean; q += x * x; }
    red[tid] = q; __syncthreads();
    for (int off = 64; off > 0; off >>= 1) {
        if (tid < off) red[tid] += red[tid + off];
        __syncthreads();
    }
    float inv = 1.0f / sqrtf(red[0] * (1.0f / 512.0f) + 1e-5f);
    float* dst = d_cs + (size_t)row * 512;
    for (int d = tid; d < 512; d += 128) dst[d] = (sv[d] - mean) * inv * g[d] + beta[d];
    if (tid == 0) d_idx[row] = row & 63;
}

// ---------------- pair scorer (one warp per pair) ----------------
__device__ __forceinline__ void score_pair(
    int n, int j, int lane,
    const float* Wd1s, const float* Wd2s, const float* bd1s, float bd2v,
    float* fsrow, float* lg)
{
    int a  = d_idx[n * 64 + j];
    int bs = d_idx[n * 64 + j + 1];
    const float* lrow = d_cs + (size_t)(n * 64 + a) * 512;
    const float* rrow = d_cs + (size_t)(n * 64 + bs) * 512;
    for (int t = lane; t < 128; t += 32)
        fsrow[t] = (t < 64) ? lrow[t] : rrow[t - 64];
    __syncwarp();
    float acc0 = 0.0f, acc1 = 0.0f;
#pragma unroll 16
    for (int k = 0; k < 128; k++) {
        float f = fsrow[k];
        acc0 = fmaf(f, Wd1s[k * 64 + lane], acc0);
        acc1 = fmaf(f, Wd1s[k * 64 + lane + 32], acc1);
    }
    float h0 = gelu_f(acc0 + bd1s[lane]);
    float h1 = gelu_f(acc1 + bd1s[lane + 32]);
    float part = h0 * Wd2s[lane] + h1 * Wd2s[lane + 32];
#pragma unroll
    for (int off = 16; off > 0; off >>= 1)
        part += __shfl_xor_sync(0xffffffffu, part, off);
    if (lane == 0) {
        float raw = part + bd2v;
        lg[j] = raw;
        d_logits[n * 64 + j] = raw;
    }
    __syncwarp();
}

// ---------------- fused (prev gate+LN) + incremental scorer + argmax + compaction ----------------
// One block of 256 threads per batch row. Logits are cached across iterations:
// after merging pair k only pairs k-1 and k change (bitwise-identical reuse of
// the rest), so it>0 recomputes at most 2 pairs. Mask gating applied at argmax.
__global__ __launch_bounds__(256) void select_k(
    const float* __restrict__ Wd1, const float* __restrict__ bd1,
    const float* __restrict__ Wd2, const float* __restrict__ bd2,
    const float* __restrict__ mask,
    const float* __restrict__ b2, const float* __restrict__ g,
    const float* __restrict__ beta,
    int it, int P, int force0, int do_ln)
{
    int n = blockIdx.x;
    int tid = threadIdx.x, w = tid >> 5, lane = tid & 31;
    __shared__ float Wd1s[128 * 64];
    __shared__ float Wd2s[64];
    __shared__ float bd1s[64];
    __shared__ float fs[8][128];
    __shared__ float lg[64];
    __shared__ float sv[512];
    __shared__ float red[256];
    __shared__ unsigned long long wmax[8];
    __shared__ int shk[4];   // k, sL, sR, flag

    // ---- phase 0: previous iteration's gate + LayerNorm ----
    if (do_ln && d_flag[n] != 0) {
        const float* base = d_part + (size_t)n * 2048;
        for (int d = tid; d < 512; d += 256) {
            float c0 = 0.0f, c1 = 0.0f, c2 = 0.0f, c3 = 0.0f;
#pragma unroll
            for (int z = 0; z < SPLITK2; z++) {
                const float* pp = base + (size_t)z * (NB * CHD);
                c0 += pp[d]; c1 += pp[512 + d]; c2 += pp[1024 + d]; c3 += pp[1536 + d];
            }
            c0 += b2[d]; c1 += b2[512 + d]; c2 += b2[1024 + d]; c3 += b2[1536 + d];
            float l = d_xcat[(size_t)n * 1024 + d];
            float r = d_xcat[(size_t)n * 1024 + 512 + d];
            sv[d] = sigm_f(c0) * l + sigm_f(c1) * r + sigm_f(c2) * c3;
        }
        __syncthreads();
        float p = sv[tid] + sv[tid + 256];
        red[tid] = p; __syncthreads();
        for (int off = 128; off > 0; off >>= 1) {
            if (tid < off) red[tid] += red[tid + off];
            __syncthreads();
        }
        float mean = red[0] * (1.0f / 512.0f);
        __syncthreads();
        float d0 = sv[tid] - mean, d1 = sv[tid + 256] - mean;
        red[tid] = d0 * d0 + d1 * d1; __syncthreads();
        for (int off = 128; off > 0; off >>= 1) {
            if (tid < off) red[tid] += red[tid + off];
            __syncthreads();
        }
        float inv = 1.0f / sqrtf(red[0] * (1.0f / 512.0f) + 1e-5f);
        float* dst = d_cs + (size_t)(n * 64 + d_slotL[n]) * 512;
        for (int d = tid; d < 512; d += 256)
            dst[d] = (sv[d] - mean) * inv * g[d] + beta[d];
        __syncthreads();
    }

    // preload successor index BEFORE any compaction writes
    int mynext = (tid < 63) ? d_idx[n * 64 + tid + 1] : 0;

    // ---- phase 1: scorer (full at it==0, incremental afterwards) ----
    if (!force0) {
        for (int t = tid; t < 128 * 64; t += 256) Wd1s[t] = Wd1[t];
        if (tid < 64) { Wd2s[tid] = Wd2[tid]; bd1s[tid] = bd1[tid]; }
        if (it > 0 && tid < P) lg[tid] = d_logits[n * 64 + tid];
        __syncthreads();
        float bd2v = bd2[0];
        if (it == 0) {
            for (int j = w; j < P; j += 8)
                score_pair(n, j, lane, Wd1s, Wd2s, bd1s, bd2v, fs[w], lg);
        } else {
            int pk = d_prevk[n];
            if (w < 2) {
                int j = pk - 1 + w;
                if (j >= 0 && j < P)
                    score_pair(n, j, lane, Wd1s, Wd2s, bd1s, bd2v, fs[w], lg);
            }
        }
        __syncthreads();
    }

    // ---- phase 2: argmax with mask gating + first-index tie-break ----
    unsigned long long key = 0ull;
    if (!force0 && tid < P) {
        float mv = mask[n * 64 + it + 1 + tid];
        float v = (mv > 0.0f) ? lg[tid] : -1e9f;
        unsigned u = __float_as_uint(v);
        u = (u & 0x80000000u) ? ~u : (u | 0x80000000u);
        key = ((unsigned long long)u << 32) | (unsigned)(63 - tid);
    }
#pragma unroll
    for (int off = 16; off > 0; off >>= 1) {
        unsigned long long o = __shfl_xor_sync(0xffffffffu, key, off);
        if (o > key) key = o;
    }
    if (lane == 0) wmax[w] = key;
    __syncthreads();

    if (tid == 0) {
        unsigned long long best = wmax[0];
#pragma unroll
        for (int i = 1; i < 8; i++) if (wmax[i] > best) best = wmax[i];
        int k = force0 ? 0 : (63 - (int)(best & 0xFFFFFFFFu));
        float done = mask[n * 64 + it + 1];
        int sL = d_idx[n * 64 + k];
        int sR = d_idx[n * 64 + k + 1];
        int fl = (done > 0.0f) ? 1 : 0;
        if (!fl) { sL = d_idx[n * 64]; sR = d_idx[n * 64 + 1]; }
        shk[0] = k; shk[1] = sL; shk[2] = sR; shk[3] = fl;
        d_slotL[n] = sL; d_flag[n] = fl;
        d_prevk[n] = fl ? k : -1000;
    }
    __syncthreads();

    // ---- phase 3: compaction (idx + logits) + xcat gather ----
    float mylgnext = (tid < 63) ? d_logits[n * 64 + tid + 1] : 0.0f;
    __syncthreads();   // all reads before any shifted writes
    if (shk[3]) {
        if (tid >= shk[0] + 1 && tid <= P - 1) d_idx[n * 64 + tid] = mynext;
        if (tid >= shk[0] + 1 && tid <= P - 2) d_logits[n * 64 + tid] = mylgnext;
    }

    int sL = shk[1], sR = shk[2];
    const float* lrow = d_cs + (size_t)(n * 64 + sL) * 512;
    const float* rrow = d_cs + (size_t)(n * 64 + sR) * 512;
    float* x = d_xcat + (size_t)n * 1024;
    for (int t = tid; t < 512; t += 256) {
        x[t] = lrow[t];
        x[512 + t] = rrow[t];
    }
}

// ---------------- final fc2 reduce + gates + LayerNorm (last iteration only) ----------------
__global__ void gateln_k(const float* __restrict__ b2, const float* __restrict__ g,
                         const float* __restrict__ beta)
{
    int n = blockIdx.x;
    if (d_flag[n] == 0) return;
    int tid = threadIdx.x;   // 256
    __shared__ float sv[512];
    __shared__ float red[256];
    const float* base = d_part + (size_t)n * 2048;
    for (int d = tid; d < 512; d += 256) {
        float c0 = 0.0f, c1 = 0.0f, c2 = 0.0f, c3 = 0.0f;
#pragma unroll
        for (int z = 0; z < SPLITK2; z++) {
            const float* pp = base + (size_t)z * (NB * CHD);
            c0 += pp[d]; c1 += pp[512 + d]; c2 += pp[1024 + d]; c3 += pp[1536 + d];
        }
        c0 += b2[d]; c1 += b2[512 + d]; c2 += b2[1024 + d]; c3 += b2[1536 + d];
        float l = d_xcat[(size_t)n * 1024 + d];
        float r = d_xcat[(size_t)n * 1024 + 512 + d];
        sv[d] = sigm_f(c0) * l + sigm_f(c1) * r + sigm_f(c2) * c3;
    }
    __syncthreads();
    float p = sv[tid] + sv[tid + 256];
    red[tid] = p; __syncthreads();
    for (int off = 128; off > 0; off >>= 1) {
        if (tid < off) red[tid] += red[tid + off];
        __syncthreads();
    }
    float mean = red[0] * (1.0f / 512.0f);
    __syncthreads();
    float d0 = sv[tid] - mean, d1 = sv[tid + 256] - mean;
    red[tid] = d0 * d0 + d1 * d1; __syncthreads();
    for (int off = 128; off > 0; off >>= 1) {
        if (tid < off) red[tid] += red[tid + off];
        __syncthreads();
    }
    float inv = 1.0f / sqrtf(red[0] * (1.0f / 512.0f) + 1e-5f);
    float* dst = d_cs + (size_t)(n * 64 + d_slotL[n]) * 512;
    for (int d = tid; d < 512; d += 256)
        dst[d] = (sv[d] - mean) * inv * g[d] + beta[d];
}

// ---------------- final gather: out[n] = cs[n, idx[n][0]] ----------------
__global__ void gather_k(float* __restrict__ out)
{
    int n = blockIdx.x;
    int s0 = d_idx[n * 64];
    const float* src = d_cs + (size_t)(n * 64 + s0) * 512;
    for (int d = threadIdx.x; d < 512; d += 256)
        out[(size_t)n * 512 + d] = src[d];
}

// ---------------- host launcher (graph-capturable: kernel launches only) ----------------
extern "C" void kernel_launch(void* const* d_in, const int* in_sizes, int n_in,
                              void* d_out, int out_size)
{
    const float* input     = (const float*)d_in[0];
    const float* mask      = (const float*)d_in[1];
    const float* W_init    = (const float*)d_in[2];
    const float* b_init    = (const float*)d_in[3];
    const float* g_init    = (const float*)d_in[4];
    const float* beta_init = (const float*)d_in[5];
    const float* W_d1      = (const float*)d_in[6];
    const float* b_d1      = (const float*)d_in[7];
    const float* W_d2      = (const float*)d_in[8];
    const float* b_d2      = (const float*)d_in[9];
    const float* W_c1      = (const float*)d_in[10];
    const float* b_c1      = (const float*)d_in[11];
    const float* W_c2      = (const float*)d_in[12];
    const float* b_c2      = (const float*)d_in[13];
    const float* g_c       = (const float*)d_in[14];
    const float* beta_c    = (const float*)d_in[15];

    float *p_C0, *p_part, *p_h;
    cudaGetSymbolAddress((void**)&p_C0,   d_C0);
    cudaGetSymbolAddress((void**)&p_part, d_part);
    cudaGetSymbolAddress((void**)&p_h,    d_h);

    // init: cs = LN(input @ W_init + b_init)
    sgemm_k<<<dim3(4, 64, 1), 256>>>(input, W_init, p_C0, 8192, 512, 512, 512);
    init_ln_k<<<8192, 128>>>(b_init, g_init, beta_init);

    for (int i = 0; i < 63; i++) {
        int P = 63 - i;
        // select also completes iteration i-1's gate+LN (do_ln = i>0)
        select_k<<<NB, 256>>>(W_d1, b_d1, W_d2, b_d2, mask,
                              b_c2, g_c, beta_c,
                              i, P, (i == 62) ? 1 : 0, (i > 0) ? 1 : 0);
        // fc1 with fused split-K reduce + bias + gelu
        fc1_k<<<dim3(16, 1, SPLITK1), 256>>>(W_c1, b_c1);
        // fc2: h(128x2048) @ W_c2(2048x2048), split-K=16 (chunks of 128)
        sgemm_k<<<dim3(16, 1, SPLITK2), 256>>>(p_h, W_c2, p_part, 128, 2048, 2048, 128);
    }
    gateln_k<<<NB, 256>>>(b_c2, g_c, beta_c);   // last iteration's gate+LN
    gather_k<<<NB, 256>>>((float*)d_out);
}

// round 13
// speedup vs baseline: 1.2834x; 1.0454x over previous
#include <cuda_runtime.h>
#include <math.h>

// Problem constants
#define NB 128       // batch
#define GRID 256
#define THREADS 256
#define SPLITK 16    // split-K for both fc1 and fc2

// ---------------- device scratch (no allocations allowed) ----------------
__device__ float d_cs[NB * 64 * 512];         // chart states, slot-addressed
__device__ float d_C0[NB * 64 * 512];         // init GEMM output
__device__ float d_part[SPLITK * NB * 2048];  // split-K partial sums (fc1/fc2)
__device__ float d_h[NB * 2048];              // fc1 activations
__device__ float d_xcat[NB * 1024];           // [l, r] concat for selected pairs
__device__ float d_logits[NB * 64];           // cached raw pair logits
__device__ int   d_idx[NB * 64];              // active slot list per row
__device__ int   d_slotL[NB];
__device__ int   d_flag[NB];
__device__ int   d_prevk[NB];
__device__ unsigned int g_cnt = 0;            // grid barrier counter
__device__ unsigned int g_gen = 0;            // grid barrier generation

struct GemmS { float As[2][16][128]; float Bs[2][16][128]; };   // 32 KB
struct SelS  { float fs[8][128]; float sv[512]; float red[256];
               float lg[64]; unsigned long long wmax[8]; int shk[4]; };
union SmemU  { GemmS g; SelS s; };

__device__ __forceinline__ float gelu_f(float x) {
    float x3 = x * x * x;
    return 0.5f * x * (1.0f + tanhf(0.7978845608028654f * (x + 0.044715f * x3)));
}
__device__ __forceinline__ float sigm_f(float x) {
    return 1.0f / (1.0f + expf(-x));
}

// ---------------- device-wide barrier (all GRID blocks resident) ----------------
__device__ __forceinline__ void gsync() {
    __syncthreads();
    if (threadIdx.x == 0) {
        __threadfence();
        unsigned int g = *(volatile unsigned int*)&g_gen;
        if (atomicAdd(&g_cnt, 1u) == GRID - 1u) {
            g_cnt = 0u;
            __threadfence();
            *(volatile unsigned int*)&g_gen = g + 1u;
        } else {
            while (*(volatile unsigned int*)&g_gen == g) __nanosleep(32);
        }
        __threadfence();
    }
    __syncthreads();
}

// ---------------- 128x128 GEMM tile, double-buffered, packed f32x2 ----------------
// A: (.)xK row-major, B: KxN row-major. Computes C[m0:m0+128, n0:n0+128] over
// K-range [k0, k0+kc) into Co (leading dim N). Bit-identical per-lane rounding.
__device__ __forceinline__ void gemm_tile(
    const float* __restrict__ A, const float* __restrict__ B, float* __restrict__ Co,
    int N, int K, int m0, int n0, int k0, int kc, GemmS* sm)
{
    const int tid = threadIdx.x;
    const int tx = tid & 15;
    const int ty = tid >> 4;
    const int nk = kc >> 4;

    unsigned long long accp[8][4];
#pragma unroll
    for (int i = 0; i < 8; i++)
#pragma unroll
        for (int j = 0; j < 4; j++) accp[i][j] = 0ull;

    const int arow = tid >> 2;
    const int ac4  = (tid & 3) << 2;
    const int brow = tid >> 5;
    const int bc4  = (tid & 31) << 2;

    const float* Ap = A + (size_t)(m0 + arow) * K + k0 + ac4;
    const float* Bp = B + (size_t)(k0 + brow) * N + n0 + bc4;

    float4 ta0 = *(const float4*)(Ap);
    float4 ta1 = *(const float4*)(Ap + (size_t)64 * K);
    float4 tb0 = *(const float4*)(Bp);
    float4 tb1 = *(const float4*)(Bp + (size_t)8 * N);
    sm->As[0][ac4 + 0][arow] = ta0.x; sm->As[0][ac4 + 1][arow] = ta0.y;
    sm->As[0][ac4 + 2][arow] = ta0.z; sm->As[0][ac4 + 3][arow] = ta0.w;
    sm->As[0][ac4 + 0][arow + 64] = ta1.x; sm->As[0][ac4 + 1][arow + 64] = ta1.y;
    sm->As[0][ac4 + 2][arow + 64] = ta1.z; sm->As[0][ac4 + 3][arow + 64] = ta1.w;
    *(float4*)&sm->Bs[0][brow][bc4]     = tb0;
    *(float4*)&sm->Bs[0][brow + 8][bc4] = tb1;
    __syncthreads();

    int buf = 0;
    for (int t = 0; t < nk; t++) {
        if (t + 1 < nk) {
            const float* Apn = Ap + (t + 1) * 16;
            const float* Bpn = Bp + (size_t)(t + 1) * 16 * N;
            ta0 = *(const float4*)(Apn);
            ta1 = *(const float4*)(Apn + (size_t)64 * K);
            tb0 = *(const float4*)(Bpn);
            tb1 = *(const float4*)(Bpn + (size_t)8 * N);
        }
#pragma unroll
        for (int kk = 0; kk < 16; kk++) {
            float av[8];
            unsigned long long avp[8], bvp[4];
            *(float4*)(av)     = *(const float4*)&sm->As[buf][kk][ty * 8];
            *(float4*)(av + 4) = *(const float4*)&sm->As[buf][kk][ty * 8 + 4];
            *(ulonglong2*)(bvp + 0) = *(const ulonglong2*)&sm->Bs[buf][kk][tx * 8 + 0];
            *(ulonglong2*)(bvp + 2) = *(const ulonglong2*)&sm->Bs[buf][kk][tx * 8 + 4];
#pragma unroll
            for (int i = 0; i < 8; i++)
                asm("mov.b64 %0, {%1, %1};" : "=l"(avp[i]) : "f"(av[i]));
#pragma unroll
            for (int i = 0; i < 8; i++)
#pragma unroll
                for (int j = 0; j < 4; j++)
                    asm("fma.rn.f32x2 %0, %1, %2, %0;"
                        : "+l"(accp[i][j]) : "l"(avp[i]), "l"(bvp[j]));
        }
        if (t + 1 < nk) {
            int nb = buf ^ 1;
            sm->As[nb][ac4 + 0][arow] = ta0.x; sm->As[nb][ac4 + 1][arow] = ta0.y;
            sm->As[nb][ac4 + 2][arow] = ta0.z; sm->As[nb][ac4 + 3][arow] = ta0.w;
            sm->As[nb][ac4 + 0][arow + 64] = ta1.x; sm->As[nb][ac4 + 1][arow + 64] = ta1.y;
            sm->As[nb][ac4 + 2][arow + 64] = ta1.z; sm->As[nb][ac4 + 3][arow + 64] = ta1.w;
            *(float4*)&sm->Bs[nb][brow][bc4]     = tb0;
            *(float4*)&sm->Bs[nb][brow + 8][bc4] = tb1;
            __syncthreads();
            buf = nb;
        }
    }

#pragma unroll
    for (int i = 0; i < 8; i++) {
        ulonglong2 v0 = make_ulonglong2(accp[i][0], accp[i][1]);
        ulonglong2 v1 = make_ulonglong2(accp[i][2], accp[i][3]);
        *(ulonglong2*)(Co + (size_t)(m0 + ty * 8 + i) * N + n0 + tx * 8)     = v0;
        *(ulonglong2*)(Co + (size_t)(m0 + ty * 8 + i) * N + n0 + tx * 8 + 4) = v1;
    }
}

// ---------------- fc2 split-K reduce + gates + LayerNorm into cs[sL] ----------------
__device__ void gate_ln(int n, const float* __restrict__ b2, const float* __restrict__ g,
                        const float* __restrict__ beta, SelS* sm)
{
    int tid = threadIdx.x;
    float* sv = sm->sv; float* red = sm->red;
    const float* base = d_part + (size_t)n * 2048;
    for (int d = tid; d < 512; d += 256) {
        float c0 = 0.f, c1 = 0.f, c2 = 0.f, c3 = 0.f;
#pragma unroll
        for (int z = 0; z < SPLITK; z++) {
            const float* pp = base + (size_t)z * (NB * 2048);
            c0 += pp[d]; c1 += pp[512 + d]; c2 += pp[1024 + d]; c3 += pp[1536 + d];
        }
        c0 += b2[d]; c1 += b2[512 + d]; c2 += b2[1024 + d]; c3 += b2[1536 + d];
        float l = d_xcat[(size_t)n * 1024 + d];
        float r = d_xcat[(size_t)n * 1024 + 512 + d];
        sv[d] = sigm_f(c0) * l + sigm_f(c1) * r + sigm_f(c2) * c3;
    }
    __syncthreads();
    float p = sv[tid] + sv[tid + 256];
    red[tid] = p; __syncthreads();
    for (int off = 128; off > 0; off >>= 1) {
        if (tid < off) red[tid] += red[tid + off];
        __syncthreads();
    }
    float mean = red[0] * (1.0f / 512.0f);
    __syncthreads();
    float d0 = sv[tid] - mean, d1 = sv[tid + 256] - mean;
    red[tid] = d0 * d0 + d1 * d1; __syncthreads();
    for (int off = 128; off > 0; off >>= 1) {
        if (tid < off) red[tid] += red[tid + off];
        __syncthreads();
    }
    float inv = 1.0f / sqrtf(red[0] * (1.0f / 512.0f) + 1e-5f);
    float* dst = d_cs + (size_t)(n * 64 + d_slotL[n]) * 512;
    for (int d = tid; d < 512; d += 256)
        dst[d] = (sv[d] - mean) * inv * g[d] + beta[d];
    __syncthreads();
}

// ---------------- pair scorer (one warp per pair; weights from L2) ----------------
__device__ __forceinline__ void score_pair_g(
    int n, int j, int lane,
    const float* __restrict__ Wd1, const float* __restrict__ Wd2,
    const float* __restrict__ bd1, float bd2v, float* fsrow, float* lg)
{
    int a  = d_idx[n * 64 + j];
    int bs = d_idx[n * 64 + j + 1];
    const float* lrow = d_cs + (size_t)(n * 64 + a) * 512;
    const float* rrow = d_cs + (size_t)(n * 64 + bs) * 512;
    for (int t = lane; t < 128; t += 32)
        fsrow[t] = (t < 64) ? lrow[t] : rrow[t - 64];
    __syncwarp();
    float acc0 = 0.0f, acc1 = 0.0f;
#pragma unroll 8
    for (int k = 0; k < 128; k++) {
        float f = fsrow[k];
        acc0 = fmaf(f, Wd1[k * 64 + lane], acc0);
        acc1 = fmaf(f, Wd1[k * 64 + lane + 32], acc1);
    }
    float h0 = gelu_f(acc0 + bd1[lane]);
    float h1 = gelu_f(acc1 + bd1[lane + 32]);
    float part = h0 * Wd2[lane] + h1 * Wd2[lane + 32];
#pragma unroll
    for (int off = 16; off > 0; off >>= 1)
        part += __shfl_xor_sync(0xffffffffu, part, off);
    if (lane == 0) {
        float raw = part + bd2v;
        lg[j] = raw;
        d_logits[n * 64 + j] = raw;
    }
    __syncwarp();
}

// ---------------- select phase: prev gate+LN, incremental scorer, argmax, compact ----------------
__device__ void select_phase(
    int n, const float* __restrict__ Wd1, const float* __restrict__ bd1,
    const float* __restrict__ Wd2, const float* __restrict__ bd2,
    const float* __restrict__ mask, const float* __restrict__ b2,
    const float* __restrict__ gc, const float* __restrict__ bc,
    int it, int P, int force0, int do_ln, SelS* sm)
{
    int tid = threadIdx.x, w = tid >> 5, lane = tid & 31;

    if (do_ln && d_flag[n] != 0)
        gate_ln(n, b2, gc, bc, sm);

    int mynext = (tid < 63) ? d_idx[n * 64 + tid + 1] : 0;

    if (!force0) {
        if (it > 0 && tid < P) sm->lg[tid] = d_logits[n * 64 + tid];
        __syncthreads();
        float bd2v = bd2[0];
        if (it == 0) {
            for (int j = w; j < P; j += 8)
                score_pair_g(n, j, lane, Wd1, Wd2, bd1, bd2v, sm->fs[w], sm->lg);
        } else {
            int pk = d_prevk[n];
            if (w < 2) {
                int j = pk - 1 + w;
                if (j >= 0 && j < P)
                    score_pair_g(n, j, lane, Wd1, Wd2, bd1, bd2v, sm->fs[w], sm->lg);
            }
        }
        __syncthreads();
    }

    // argmax with mask gating + first-index tie-break
    unsigned long long key = 0ull;
    if (!force0 && tid < P) {
        float mv = mask[n * 64 + it + 1 + tid];
        float v = (mv > 0.0f) ? sm->lg[tid] : -1e9f;
        unsigned u = __float_as_uint(v);
        u = (u & 0x80000000u) ? ~u : (u | 0x80000000u);
        key = ((unsigned long long)u << 32) | (unsigned)(63 - tid);
    }
#pragma unroll
    for (int off = 16; off > 0; off >>= 1) {
        unsigned long long o = __shfl_xor_sync(0xffffffffu, key, off);
        if (o > key) key = o;
    }
    if (lane == 0) sm->wmax[w] = key;
    __syncthreads();

    if (tid == 0) {
        unsigned long long best = sm->wmax[0];
#pragma unroll
        for (int ii = 1; ii < 8; ii++) if (sm->wmax[ii] > best) best = sm->wmax[ii];
        int k = force0 ? 0 : (63 - (int)(best & 0xFFFFFFFFu));
        float done = mask[n * 64 + it + 1];
        int sL = d_idx[n * 64 + k];
        int sR = d_idx[n * 64 + k + 1];
        int fl = (done > 0.0f) ? 1 : 0;
        if (!fl) { sL = d_idx[n * 64]; sR = d_idx[n * 64 + 1]; }
        sm->shk[0] = k; sm->shk[1] = sL; sm->shk[2] = sR; sm->shk[3] = fl;
        d_slotL[n] = sL; d_flag[n] = fl;
        d_prevk[n] = fl ? k : -1000;
    }
    __syncthreads();

    // compaction (idx + logits) + xcat gather
    float mylgnext = (tid < 63) ? d_logits[n * 64 + tid + 1] : 0.0f;
    __syncthreads();
    if (sm->shk[3]) {
        if (tid >= sm->shk[0] + 1 && tid <= P - 1) d_idx[n * 64 + tid] = mynext;
        if (tid >= sm->shk[0] + 1 && tid <= P - 2) d_logits[n * 64 + tid] = mylgnext;
    }

    int sL = sm->shk[1], sR = sm->shk[2];
    const float* lrow = d_cs + (size_t)(n * 64 + sL) * 512;
    const float* rrow = d_cs + (size_t)(n * 64 + sR) * 512;
    float* x = d_xcat + (size_t)n * 1024;
    for (int t = tid; t < 512; t += 256) {
        x[t] = lrow[t];
        x[512 + t] = rrow[t];
    }
}

// ---------------- the persistent kernel ----------------
__global__ __launch_bounds__(THREADS, 2) void persist_k(
    const float* __restrict__ input, const float* __restrict__ mask,
    const float* __restrict__ W_init, const float* __restrict__ b_init,
    const float* __restrict__ g_init, const float* __restrict__ beta_init,
    const float* __restrict__ W_d1, const float* __restrict__ b_d1,
    const float* __restrict__ W_d2, const float* __restrict__ b_d2,
    const float* __restrict__ W_c1, const float* __restrict__ b_c1,
    const float* __restrict__ W_c2, const float* __restrict__ b_c2,
    const float* __restrict__ g_c, const float* __restrict__ beta_c,
    float* __restrict__ out)
{
    __shared__ __align__(16) SmemU su;
    const int bid = blockIdx.x;
    const int tid = threadIdx.x;

    // ---- init GEMM: C0 = input @ W_init (8192x512 @ 512x512), 64 m-tiles x 4 n-tiles ----
    gemm_tile(input, W_init, d_C0, 512, 512, (bid >> 2) * 128, (bid & 3) * 128, 0, 512, &su.g);
    gsync();

    // ---- init LayerNorm + idx init: 32 rows per block ----
    {
        float* sv = su.s.sv; float* red = su.s.red;
        for (int r = 0; r < 32; r++) {
            int row = bid * 32 + r;
            const float* src = d_C0 + (size_t)row * 512;
            for (int d = tid; d < 512; d += 256) sv[d] = src[d] + b_init[d];
            __syncthreads();
            float p = sv[tid] + sv[tid + 256];
            red[tid] = p; __syncthreads();
            for (int off = 128; off > 0; off >>= 1) {
                if (tid < off) red[tid] += red[tid + off];
                __syncthreads();
            }
            float mean = red[0] * (1.0f / 512.0f);
            __syncthreads();
            float d0 = sv[tid] - mean, d1 = sv[tid + 256] - mean;
            red[tid] = d0 * d0 + d1 * d1; __syncthreads();
            for (int off = 128; off > 0; off >>= 1) {
                if (tid < off) red[tid] += red[tid + off];
                __syncthreads();
            }
            float inv = 1.0f / sqrtf(red[0] * (1.0f / 512.0f) + 1e-5f);
            float* dst = d_cs + (size_t)row * 512;
            for (int d = tid; d < 512; d += 256)
                dst[d] = (sv[d] - mean) * inv * g_init[d] + beta_init[d];
            if (tid == 0) d_idx[row] = row & 63;
            __syncthreads();
        }
    }
    gsync();

    // ---- 63 merge iterations ----
    for (int i = 0; i < 63; i++) {
        int P = 63 - i;
        if (bid < NB)
            select_phase(bid, W_d1, b_d1, W_d2, b_d2, mask, b_c2, g_c, beta_c,
                         i, P, (i == 62) ? 1 : 0, (i > 0) ? 1 : 0, &su.s);
        gsync();

        // fc1 partials: xcat(128x1024) @ W_c1(1024x2048), 16 n-tiles x 16 z
        gemm_tile(d_xcat, W_c1, d_part + (size_t)(bid >> 4) * (NB * 2048),
                  2048, 1024, 0, (bid & 15) * 128, (bid >> 4) * 64, 64, &su.g);
        gsync();

        // fc1 split-K reduce + bias + gelu: one float4 per thread
        {
            size_t off = ((size_t)bid * 256 + tid) * 4;
            int c4 = (int)(off & 2047);
            float4 s = *(const float4*)(d_part + off);
#pragma unroll
            for (int z = 1; z < SPLITK; z++) {
                float4 p = *(const float4*)(d_part + (size_t)z * (NB * 2048) + off);
                s.x += p.x; s.y += p.y; s.z += p.z; s.w += p.w;
            }
            float4 bb = *(const float4*)(b_c1 + c4);
            s.x = gelu_f(s.x + bb.x); s.y = gelu_f(s.y + bb.y);
            s.z = gelu_f(s.z + bb.z); s.w = gelu_f(s.w + bb.w);
            *(float4*)(d_h + off) = s;
        }
        gsync();

        // fc2 partials: h(128x2048) @ W_c2(2048x2048), 16 n-tiles x 16 z
        gemm_tile(d_h, W_c2, d_part + (size_t)(bid >> 4) * (NB * 2048),
                  2048, 2048, 0, (bid & 15) * 128, (bid >> 4) * 128, 128, &su.g);
        gsync();
    }

    // ---- final gate+LN (iteration 62) ----
    if (bid < NB && d_flag[bid] != 0)
        gate_ln(bid, b_c2, g_c, beta_c, &su.s);
    gsync();

    // ---- gather: out[n] = cs[n, idx[n][0]] ----
    if (bid < NB) {
        int s0 = d_idx[bid * 64];
        const float* src = d_cs + (size_t)(bid * 64 + s0) * 512;
        for (int d = tid; d < 512; d += 256)
            out[(size_t)bid * 512 + d] = src[d];
    }
}

// ---------------- host launcher (graph-capturable: one kernel launch) ----------------
extern "C" void kernel_launch(void* const* d_in, const int* in_sizes, int n_in,
                              void* d_out, int out_size)
{
    const float* input     = (const float*)d_in[0];
    const float* mask      = (const float*)d_in[1];
    const float* W_init    = (const float*)d_in[2];
    const float* b_init    = (const float*)d_in[3];
    const float* g_init    = (const float*)d_in[4];
    const float* beta_init = (const float*)d_in[5];
    const float* W_d1      = (const float*)d_in[6];
    const float* b_d1      = (const float*)d_in[7];
    const float* W_d2      = (const float*)d_in[8];
    const float* b_d2      = (const float*)d_in[9];
    const float* W_c1      = (const float*)d_in[10];
    const float* b_c1      = (const float*)d_in[11];
    const float* W_c2      = (const float*)d_in[12];
    const float* b_c2      = (const float*)d_in[13];
    const float* g_c       = (const float*)d_in[14];
    const float* beta_c    = (const float*)d_in[15];

    persist_k<<<GRID, THREADS>>>(input, mask, W_init, b_init, g_init, beta_init,
                                 W_d1, b_d1, W_d2, b_d2, W_c1, b_c1, W_c2, b_c2,
                                 g_c, beta_c, (float*)d_out);
}

// round 14
// speedup vs baseline: 1.3252x; 1.0326x over previous
#include <cuda_runtime.h>
#include <math.h>

// Problem constants
#define NB 128       // batch
#define GRID 256
#define THREADS 256
#define SPLITK 16    // split-K for both fc1 and fc2

// ---------------- device scratch (no allocations allowed) ----------------
__device__ float d_cs[NB * 64 * 512];          // chart states, slot-addressed
__device__ float d_C0[NB * 64 * 512];          // init GEMM output
__device__ float d_part1[SPLITK * NB * 2048];  // fc1 split-K partials
__device__ float d_part2[SPLITK * NB * 2048];  // fc2 split-K partials
__device__ float d_h[NB * 2048];               // fc1 activations
__device__ float d_xcat[NB * 1024];            // [l, r] concat for selected pairs
__device__ float d_logits[NB * 64];            // cached raw pair logits
__device__ int   d_idx[NB * 64];               // active slot list per row
__device__ int   d_slotL[NB];
__device__ int   d_flag[NB];
__device__ int   d_prevk[NB];
// dataflow counters (generation-indexed, monotone within a launch)
__device__ unsigned int c_sel = 0;             // select completions (128/iter)
__device__ unsigned int c_grp[16] = {};        // fc1 group arrivals (16/iter each)
__device__ unsigned int c_red[16] = {};        // h-slice reduce completions
__device__ unsigned int c_fc2 = 0;             // fc2 job completions (256/iter)
__device__ unsigned int g_cnt = 0;             // classic grid barrier (init/final)
__device__ unsigned int g_gen = 0;

struct GemmS { float As[2][16][128]; float Bs[2][16][128]; };   // 32 KB
struct SelS  { float fs[8][128]; float sv[512]; float red[256];
               float lg[64]; unsigned long long wmax[8]; int shk[4]; };
union SmemU  { GemmS g; SelS s; };

__device__ __forceinline__ float gelu_f(float x) {
    float x3 = x * x * x;
    return 0.5f * x * (1.0f + tanhf(0.7978845608028654f * (x + 0.044715f * x3)));
}
__device__ __forceinline__ float sigm_f(float x) {
    return 1.0f / (1.0f + expf(-x));
}

// ---------------- sync primitives ----------------
__device__ __forceinline__ void gsync() {
    __syncthreads();
    if (threadIdx.x == 0) {
        __threadfence();
        unsigned int g = *(volatile unsigned int*)&g_gen;
        if (atomicAdd(&g_cnt, 1u) == GRID - 1u) {
            g_cnt = 0u;
            __threadfence();
            *(volatile unsigned int*)&g_gen = g + 1u;
        } else {
            while (*(volatile unsigned int*)&g_gen == g) __nanosleep(32);
        }
        __threadfence();
    }
    __syncthreads();
}
// all threads' prior gmem writes visible, then one arrival tick
__device__ __forceinline__ void arrive_cnt(unsigned int* c) {
    __threadfence();
    __syncthreads();
    if (threadIdx.x == 0) atomicAdd(c, 1u);
}
__device__ __forceinline__ void wait_cnt(unsigned int* c, unsigned int tgt) {
    if (threadIdx.x == 0) {
        while (*(volatile unsigned int*)c < tgt) __nanosleep(64);
        __threadfence();
    }
    __syncthreads();
}

// ---------------- 128x128 GEMM tile, double-buffered, packed f32x2 ----------------
__device__ __forceinline__ void gemm_tile(
    const float* __restrict__ A, const float* __restrict__ B, float* __restrict__ Co,
    int N, int K, int m0, int n0, int k0, int kc, GemmS* sm)
{
    const int tid = threadIdx.x;
    const int tx = tid & 15;
    const int ty = tid >> 4;
    const int nk = kc >> 4;

    unsigned long long accp[8][4];
#pragma unroll
    for (int i = 0; i < 8; i++)
#pragma unroll
        for (int j = 0; j < 4; j++) accp[i][j] = 0ull;

    const int arow = tid >> 2;
    const int ac4  = (tid & 3) << 2;
    const int brow = tid >> 5;
    const int bc4  = (tid & 31) << 2;

    const float* Ap = A + (size_t)(m0 + arow) * K + k0 + ac4;
    const float* Bp = B + (size_t)(k0 + brow) * N + n0 + bc4;

    float4 ta0 = *(const float4*)(Ap);
    float4 ta1 = *(const float4*)(Ap + (size_t)64 * K);
    float4 tb0 = *(const float4*)(Bp);
    float4 tb1 = *(const float4*)(Bp + (size_t)8 * N);
    sm->As[0][ac4 + 0][arow] = ta0.x; sm->As[0][ac4 + 1][arow] = ta0.y;
    sm->As[0][ac4 + 2][arow] = ta0.z; sm->As[0][ac4 + 3][arow] = ta0.w;
    sm->As[0][ac4 + 0][arow + 64] = ta1.x; sm->As[0][ac4 + 1][arow + 64] = ta1.y;
    sm->As[0][ac4 + 2][arow + 64] = ta1.z; sm->As[0][ac4 + 3][arow + 64] = ta1.w;
    *(float4*)&sm->Bs[0][brow][bc4]     = tb0;
    *(float4*)&sm->Bs[0][brow + 8][bc4] = tb1;
    __syncthreads();

    int buf = 0;
    for (int t = 0; t < nk; t++) {
        if (t + 1 < nk) {
            const float* Apn = Ap + (t + 1) * 16;
            const float* Bpn = Bp + (size_t)(t + 1) * 16 * N;
            ta0 = *(const float4*)(Apn);
            ta1 = *(const float4*)(Apn + (size_t)64 * K);
            tb0 = *(const float4*)(Bpn);
            tb1 = *(const float4*)(Bpn + (size_t)8 * N);
        }
#pragma unroll
        for (int kk = 0; kk < 16; kk++) {
            float av[8];
            unsigned long long avp[8], bvp[4];
            *(float4*)(av)     = *(const float4*)&sm->As[buf][kk][ty * 8];
            *(float4*)(av + 4) = *(const float4*)&sm->As[buf][kk][ty * 8 + 4];
            *(ulonglong2*)(bvp + 0) = *(const ulonglong2*)&sm->Bs[buf][kk][tx * 8 + 0];
            *(ulonglong2*)(bvp + 2) = *(const ulonglong2*)&sm->Bs[buf][kk][tx * 8 + 4];
#pragma unroll
            for (int i = 0; i < 8; i++)
                asm("mov.b64 %0, {%1, %1};" : "=l"(avp[i]) : "f"(av[i]));
#pragma unroll
            for (int i = 0; i < 8; i++)
#pragma unroll
                for (int j = 0; j < 4; j++)
                    asm("fma.rn.f32x2 %0, %1, %2, %0;"
                        : "+l"(accp[i][j]) : "l"(avp[i]), "l"(bvp[j]));
        }
        if (t + 1 < nk) {
            int nb = buf ^ 1;
            sm->As[nb][ac4 + 0][arow] = ta0.x; sm->As[nb][ac4 + 1][arow] = ta0.y;
            sm->As[nb][ac4 + 2][arow] = ta0.z; sm->As[nb][ac4 + 3][arow] = ta0.w;
            sm->As[nb][ac4 + 0][arow + 64] = ta1.x; sm->As[nb][ac4 + 1][arow + 64] = ta1.y;
            sm->As[nb][ac4 + 2][arow + 64] = ta1.z; sm->As[nb][ac4 + 3][arow + 64] = ta1.w;
            *(float4*)&sm->Bs[nb][brow][bc4]     = tb0;
            *(float4*)&sm->Bs[nb][brow + 8][bc4] = tb1;
            __syncthreads();
            buf = nb;
        }
    }

#pragma unroll
    for (int i = 0; i < 8; i++) {
        ulonglong2 v0 = make_ulonglong2(accp[i][0], accp[i][1]);
        ulonglong2 v1 = make_ulonglong2(accp[i][2], accp[i][3]);
        *(ulonglong2*)(Co + (size_t)(m0 + ty * 8 + i) * N + n0 + tx * 8)     = v0;
        *(ulonglong2*)(Co + (size_t)(m0 + ty * 8 + i) * N + n0 + tx * 8 + 4) = v1;
    }
}

// ---------------- fc2 split-K reduce + gates + LayerNorm into cs[sL] ----------------
__device__ void gate_ln(int n, const float* __restrict__ b2, const float* __restrict__ g,
                        const float* __restrict__ beta, SelS* sm)
{
    int tid = threadIdx.x;
    float* sv = sm->sv; float* red = sm->red;
    const float* base = d_part2 + (size_t)n * 2048;
    for (int d = tid; d < 512; d += 256) {
        float c0 = 0.f, c1 = 0.f, c2 = 0.f, c3 = 0.f;
#pragma unroll
        for (int z = 0; z < SPLITK; z++) {
            const float* pp = base + (size_t)z * (NB * 2048);
            c0 += pp[d]; c1 += pp[512 + d]; c2 += pp[1024 + d]; c3 += pp[1536 + d];
        }
        c0 += b2[d]; c1 += b2[512 + d]; c2 += b2[1024 + d]; c3 += b2[1536 + d];
        float l = d_xcat[(size_t)n * 1024 + d];
        float r = d_xcat[(size_t)n * 1024 + 512 + d];
        sv[d] = sigm_f(c0) * l + sigm_f(c1) * r + sigm_f(c2) * c3;
    }
    __syncthreads();
    float p = sv[tid] + sv[tid + 256];
    red[tid] = p; __syncthreads();
    for (int off = 128; off > 0; off >>= 1) {
        if (tid < off) red[tid] += red[tid + off];
        __syncthreads();
    }
    float mean = red[0] * (1.0f / 512.0f);
    __syncthreads();
    float d0 = sv[tid] - mean, d1 = sv[tid + 256] - mean;
    red[tid] = d0 * d0 + d1 * d1; __syncthreads();
    for (int off = 128; off > 0; off >>= 1) {
        if (tid < off) red[tid] += red[tid + off];
        __syncthreads();
    }
    float inv = 1.0f / sqrtf(red[0] * (1.0f / 512.0f) + 1e-5f);
    float* dst = d_cs + (size_t)(n * 64 + d_slotL[n]) * 512;
    for (int d = tid; d < 512; d += 256)
        dst[d] = (sv[d] - mean) * inv * g[d] + beta[d];
    __syncthreads();
}

// ---------------- pair scorer (one warp per pair; weights from L2) ----------------
__device__ __forceinline__ void score_pair_g(
    int n, int j, int lane,
    const float* __restrict__ Wd1, const float* __restrict__ Wd2,
    const float* __restrict__ bd1, float bd2v, float* fsrow, float* lg)
{
    int a  = d_idx[n * 64 + j];
    int bs = d_idx[n * 64 + j + 1];
    const float* lrow = d_cs + (size_t)(n * 64 + a) * 512;
    const float* rrow = d_cs + (size_t)(n * 64 + bs) * 512;
    for (int t = lane; t < 128; t += 32)
        fsrow[t] = (t < 64) ? lrow[t] : rrow[t - 64];
    __syncwarp();
    float acc0 = 0.0f, acc1 = 0.0f;
#pragma unroll 8
    for (int k = 0; k < 128; k++) {
        float f = fsrow[k];
        acc0 = fmaf(f, Wd1[k * 64 + lane], acc0);
        acc1 = fmaf(f, Wd1[k * 64 + lane + 32], acc1);
    }
    float h0 = gelu_f(acc0 + bd1[lane]);
    float h1 = gelu_f(acc1 + bd1[lane + 32]);
    float part = h0 * Wd2[lane] + h1 * Wd2[lane + 32];
#pragma unroll
    for (int off = 16; off > 0; off >>= 1)
        part += __shfl_xor_sync(0xffffffffu, part, off);
    if (lane == 0) {
        float raw = part + bd2v;
        lg[j] = raw;
        d_logits[n * 64 + j] = raw;
    }
    __syncwarp();
}

// ---------------- select phase: prev gate+LN, incremental scorer, argmax, compact ----------------
__device__ void select_phase(
    int n, const float* __restrict__ Wd1, const float* __restrict__ bd1,
    const float* __restrict__ Wd2, const float* __restrict__ bd2,
    const float* __restrict__ mask, const float* __restrict__ b2,
    const float* __restrict__ gc, const float* __restrict__ bc,
    int it, int P, int force0, int do_ln, SelS* sm)
{
    int tid = threadIdx.x, w = tid >> 5, lane = tid & 31;

    if (do_ln && d_flag[n] != 0)
        gate_ln(n, b2, gc, bc, sm);

    int mynext = (tid < 63) ? d_idx[n * 64 + tid + 1] : 0;

    if (!force0) {
        if (it > 0 && tid < P) sm->lg[tid] = d_logits[n * 64 + tid];
        __syncthreads();
        float bd2v = bd2[0];
        if (it == 0) {
            for (int j = w; j < P; j += 8)
                score_pair_g(n, j, lane, Wd1, Wd2, bd1, bd2v, sm->fs[w], sm->lg);
        } else {
            int pk = d_prevk[n];
            if (w < 2) {
                int j = pk - 1 + w;
                if (j >= 0 && j < P)
                    score_pair_g(n, j, lane, Wd1, Wd2, bd1, bd2v, sm->fs[w], sm->lg);
            }
        }
        __syncthreads();
    }

    // argmax with mask gating + first-index tie-break
    unsigned long long key = 0ull;
    if (!force0 && tid < P) {
        float mv = mask[n * 64 + it + 1 + tid];
        float v = (mv > 0.0f) ? sm->lg[tid] : -1e9f;
        unsigned u = __float_as_uint(v);
        u = (u & 0x80000000u) ? ~u : (u | 0x80000000u);
        key = ((unsigned long long)u << 32) | (unsigned)(63 - tid);
    }
#pragma unroll
    for (int off = 16; off > 0; off >>= 1) {
        unsigned long long o = __shfl_xor_sync(0xffffffffu, key, off);
        if (o > key) key = o;
    }
    if (lane == 0) sm->wmax[w] = key;
    __syncthreads();

    if (tid == 0) {
        unsigned long long best = sm->wmax[0];
#pragma unroll
        for (int ii = 1; ii < 8; ii++) if (sm->wmax[ii] > best) best = sm->wmax[ii];
        int k = force0 ? 0 : (63 - (int)(best & 0xFFFFFFFFu));
        float done = mask[n * 64 + it + 1];
        int sL = d_idx[n * 64 + k];
        int sR = d_idx[n * 64 + k + 1];
        int fl = (done > 0.0f) ? 1 : 0;
        if (!fl) { sL = d_idx[n * 64]; sR = d_idx[n * 64 + 1]; }
        sm->shk[0] = k; sm->shk[1] = sL; sm->shk[2] = sR; sm->shk[3] = fl;
        d_slotL[n] = sL; d_flag[n] = fl;
        d_prevk[n] = fl ? k : -1000;
    }
    __syncthreads();

    // compaction (idx + logits) + xcat gather
    float mylgnext = (tid < 63) ? d_logits[n * 64 + tid + 1] : 0.0f;
    __syncthreads();
    if (sm->shk[3]) {
        if (tid >= sm->shk[0] + 1 && tid <= P - 1) d_idx[n * 64 + tid] = mynext;
        if (tid >= sm->shk[0] + 1 && tid <= P - 2) d_logits[n * 64 + tid] = mylgnext;
    }

    int sL = sm->shk[1], sR = sm->shk[2];
    const float* lrow = d_cs + (size_t)(n * 64 + sL) * 512;
    const float* rrow = d_cs + (size_t)(n * 64 + sR) * 512;
    float* x = d_xcat + (size_t)n * 1024;
    for (int t = tid; t < 512; t += 256) {
        x[t] = lrow[t];
        x[512 + t] = rrow[t];
    }
}

// ---------------- the persistent kernel ----------------
__global__ __launch_bounds__(THREADS, 2) void persist_k(
    const float* __restrict__ input, const float* __restrict__ mask,
    const float* __restrict__ W_init, const float* __restrict__ b_init,
    const float* __restrict__ g_init, const float* __restrict__ beta_init,
    const float* __restrict__ W_d1, const float* __restrict__ b_d1,
    const float* __restrict__ W_d2, const float* __restrict__ b_d2,
    const float* __restrict__ W_c1, const float* __restrict__ b_c1,
    const float* __restrict__ W_c2, const float* __restrict__ b_c2,
    const float* __restrict__ g_c, const float* __restrict__ beta_c,
    float* __restrict__ out)
{
    __shared__ __align__(16) SmemU su;
    const int bid = blockIdx.x;
    const int tid = threadIdx.x;
    const int ntile = bid & 15;   // fc1/fc2 n-tile; fc1 reduce-group id
    const int zidx  = bid >> 4;   // split-K index; member id inside reduce group

    // ---- init GEMM: C0 = input @ W_init (8192x512 @ 512x512) ----
    gemm_tile(input, W_init, d_C0, 512, 512, (bid >> 2) * 128, (bid & 3) * 128, 0, 512, &su.g);
    gsync();

    // ---- init LayerNorm + idx init: 32 rows per block ----
    {
        float* sv = su.s.sv; float* red = su.s.red;
        for (int r = 0; r < 32; r++) {
            int row = bid * 32 + r;
            const float* src = d_C0 + (size_t)row * 512;
            for (int d = tid; d < 512; d += 256) sv[d] = src[d] + b_init[d];
            __syncthreads();
            float p = sv[tid] + sv[tid + 256];
            red[tid] = p; __syncthreads();
            for (int off = 128; off > 0; off >>= 1) {
                if (tid < off) red[tid] += red[tid + off];
                __syncthreads();
            }
            float mean = red[0] * (1.0f / 512.0f);
            __syncthreads();
            float d0 = sv[tid] - mean, d1 = sv[tid + 256] - mean;
            red[tid] = d0 * d0 + d1 * d1; __syncthreads();
            for (int off = 128; off > 0; off >>= 1) {
                if (tid < off) red[tid] += red[tid + off];
                __syncthreads();
            }
            float inv = 1.0f / sqrtf(red[0] * (1.0f / 512.0f) + 1e-5f);
            float* dst = d_cs + (size_t)row * 512;
            for (int d = tid; d < 512; d += 256)
                dst[d] = (sv[d] - mean) * inv * g_init[d] + beta_init[d];
            if (tid == 0) d_idx[row] = row & 63;
            __syncthreads();
        }
    }
    gsync();

    // ---- 63 merge iterations (dataflow-synchronized) ----
    for (int i = 0; i < 63; i++) {
        int P = 63 - i;

        // SELECT: blocks 0..127 (needs ALL fc2 jobs of iter i-1)
        if (bid < NB) {
            wait_cnt(&c_fc2, 256u * (unsigned)i);
            select_phase(bid, W_d1, b_d1, W_d2, b_d2, mask, b_c2, g_c, beta_c,
                         i, P, (i == 62) ? 1 : 0, (i > 0) ? 1 : 0, &su.s);
            arrive_cnt(&c_sel);
        }

        // FC1 partials: xcat(128x1024) @ W_c1(1024x2048); job (ntile, zidx)
        wait_cnt(&c_sel, 128u * (unsigned)(i + 1));
        gemm_tile(d_xcat, W_c1, d_part1 + (size_t)zidx * (NB * 2048),
                  2048, 1024, 0, ntile * 128, zidx * 64, 64, &su.g);

        // group barrier over the 16 blocks sharing this n-tile
        arrive_cnt(&c_grp[ntile]);
        wait_cnt(&c_grp[ntile], 16u * (unsigned)(i + 1));

        // cooperative reduce of h col-slice `ntile`: member zidx does rows [8z,8z+8)
        {
            int row = zidx * 8 + (tid >> 5);
            int c4g = ntile * 128 + (tid & 31) * 4;
            size_t off = (size_t)row * 2048 + c4g;
            float4 s = *(const float4*)(d_part1 + off);
#pragma unroll
            for (int z2 = 1; z2 < SPLITK; z2++) {
                float4 p = *(const float4*)(d_part1 + (size_t)z2 * (NB * 2048) + off);
                s.x += p.x; s.y += p.y; s.z += p.z; s.w += p.w;
            }
            float4 bb = *(const float4*)(b_c1 + c4g);
            s.x = gelu_f(s.x + bb.x); s.y = gelu_f(s.y + bb.y);
            s.z = gelu_f(s.z + bb.z); s.w = gelu_f(s.w + bb.w);
            *(float4*)(d_h + off) = s;
        }
        arrive_cnt(&c_red[ntile]);

        // FC2 partials: h(128x2048) @ W_c2(2048x2048); needs only h k-slice `zidx`
        wait_cnt(&c_red[zidx], 16u * (unsigned)(i + 1));
        gemm_tile(d_h, W_c2, d_part2 + (size_t)zidx * (NB * 2048),
                  2048, 2048, 0, ntile * 128, zidx * 128, 128, &su.g);
        arrive_cnt(&c_fc2);
    }

    // ---- final gate+LN (iteration 62) + gather ----
    if (bid < NB) {
        wait_cnt(&c_fc2, 256u * 63u);
        if (d_flag[bid] != 0)
            gate_ln(bid, b_c2, g_c, beta_c, &su.s);
        int s0 = d_idx[bid * 64];
        const float* src = d_cs + (size_t)(bid * 64 + s0) * 512;
        for (int d = tid; d < 512; d += 256)
            out[(size_t)bid * 512 + d] = src[d];
    }

    // ---- reset dataflow counters for graph replay ----
    gsync();
    if (bid == 0 && tid == 0) {
        c_sel = 0u; c_fc2 = 0u;
#pragma unroll
        for (int g = 0; g < 16; g++) { c_grp[g] = 0u; c_red[g] = 0u; }
    }
}

// ---------------- host launcher (graph-capturable: one kernel launch) ----------------
extern "C" void kernel_launch(void* const* d_in, const int* in_sizes, int n_in,
                              void* d_out, int out_size)
{
    const float* input     = (const float*)d_in[0];
    const float* mask      = (const float*)d_in[1];
    const float* W_init    = (const float*)d_in[2];
    const float* b_init    = (const float*)d_in[3];
    const float* g_init    = (const float*)d_in[4];
    const float* beta_init = (const float*)d_in[5];
    const float* W_d1      = (const float*)d_in[6];
    const float* b_d1      = (const float*)d_in[7];
    const float* W_d2      = (const float*)d_in[8];
    const float* b_d2      = (const float*)d_in[9];
    const float* W_c1      = (const float*)d_in[10];
    const float* b_c1      = (const float*)d_in[11];
    const float* W_c2      = (const float*)d_in[12];
    const float* b_c2      = (const float*)d_in[13];
    const float* g_c       = (const float*)d_in[14];
    const float* beta_c    = (const float*)d_in[15];

    persist_k<<<GRID, THREADS>>>(input, mask, W_init, b_init, g_init, beta_init,
                                 W_d1, b_d1, W_d2, b_d2, W_c1, b_c1, W_c2, b_c2,
                                 g_c, beta_c, (float*)d_out);
}